// round 1
// baseline (speedup 1.0000x reference)
#include <cuda_runtime.h>

#define BB 64
#define NN 197
#define CC 768
#define HH 12
#define DD 64
#define LL 196
#define WW 72
#define MM (BB*NN)        // 12608
#define NC3 (3*CC)        // 2304
#define QSCALE 0.125f     // D^-0.5

// ---------------- scratch (static device globals; no allocs allowed) ----------
__device__ float g_Q  [BB*HH*NN*DD];   // [b][h][n][d]
__device__ float g_K  [BB*HH*NN*DD];
__device__ float g_V  [BB*HH*NN*DD];
__device__ float g_Q2 [BB*HH*NN*DD];   // transformed+scaled q
__device__ float g_TR [HH*LL*LL];      // trans[h][q][k]
__device__ float g_ATT[MM*CC];         // attention out, [b][n][c]

// ---------------- stage A: trans[h][q][k] = table[q,k,:]@params[:,h] + eye ----
__global__ __launch_bounds__(256) void trans_kernel(
    const float* __restrict__ table, const float* __restrict__ params)
{
    __shared__ float Ps[WW*HH];     // params [w][h]
    __shared__ float Ts[32][WW];
    const int q  = blockIdx.x;
    const int k0 = blockIdx.y * 32;
    const int t  = threadIdx.x;
    for (int idx = t; idx < WW*HH; idx += 256) Ps[idx] = params[idx];
    for (int idx = t; idx < 32*WW; idx += 256) {
        int kk = idx / WW, w = idx - kk*WW;
        int kg = k0 + kk;
        Ts[kk][w] = (kg < LL) ? table[(q*LL + kg)*WW + w] : 0.f;
    }
    __syncthreads();
    for (int idx = t; idx < 32*HH; idx += 256) {
        int kk = idx / HH, h = idx - kk*HH;
        int kg = k0 + kk;
        if (kg >= LL) continue;
        float s = 0.f;
        #pragma unroll
        for (int w = 0; w < WW; w++) s += Ts[kk][w] * Ps[w*HH + h];
        if (q == kg) s += 1.f;
        g_TR[(h*LL + q)*LL + kg] = s;
    }
}

// ---------------- stage B: qkv GEMM  (X[M,768] @ W[768,2304] + b) -------------
// 128x128 block tile, 16 k-tile, 256 threads, 8x8 per-thread
__global__ __launch_bounds__(256) void gemm_qkv(
    const float* __restrict__ X, const float* __restrict__ Wt,
    const float* __restrict__ bias)
{
    __shared__ float As[16][128];  // [k][m]
    __shared__ float Bs[16][128];  // [k][n]
    const int t  = threadIdx.x;
    const int tx = t & 15, ty = t >> 4;
    const int m0 = blockIdx.y * 128;
    const int n0 = blockIdx.x * 128;
    float acc[8][8];
    #pragma unroll
    for (int i = 0; i < 8; i++)
        #pragma unroll
        for (int j = 0; j < 8; j++) acc[i][j] = 0.f;

    const int arow = t >> 1;           // 0..127
    const int akb  = (t & 1) * 8;      // 0 or 8
    const int brow = t >> 4;           // 0..15
    const int bcol = (t & 15) * 8;     // 0..120

    for (int k0 = 0; k0 < CC; k0 += 16) {
        int gr = m0 + arow;
        float4 a0, a1;
        if (gr < MM) {
            const float* p = X + (long)gr*CC + k0 + akb;
            a0 = *(const float4*)p; a1 = *(const float4*)(p + 4);
        } else { a0 = make_float4(0,0,0,0); a1 = a0; }
        As[akb+0][arow]=a0.x; As[akb+1][arow]=a0.y; As[akb+2][arow]=a0.z; As[akb+3][arow]=a0.w;
        As[akb+4][arow]=a1.x; As[akb+5][arow]=a1.y; As[akb+6][arow]=a1.z; As[akb+7][arow]=a1.w;
        const float* qp = Wt + (long)(k0 + brow)*NC3 + n0 + bcol;
        float4 b0 = *(const float4*)qp;
        float4 b1 = *(const float4*)(qp + 4);
        *(float4*)&Bs[brow][bcol]   = b0;
        *(float4*)&Bs[brow][bcol+4] = b1;
        __syncthreads();
        #pragma unroll
        for (int kk = 0; kk < 16; kk++) {
            float a[8], bb[8];
            #pragma unroll
            for (int i = 0; i < 8; i++) a[i]  = As[kk][ty*8 + i];
            #pragma unroll
            for (int j = 0; j < 8; j++) bb[j] = Bs[kk][tx*8 + j];
            #pragma unroll
            for (int i = 0; i < 8; i++)
                #pragma unroll
                for (int j = 0; j < 8; j++) acc[i][j] += a[i] * bb[j];
        }
        __syncthreads();
    }
    // epilogue: scatter to Q/K/V [b][h][n][d]
    #pragma unroll
    for (int i = 0; i < 8; i++) {
        int row = m0 + ty*8 + i;
        if (row >= MM) continue;
        int b_ = row / NN, n_ = row - b_*NN;
        #pragma unroll
        for (int j = 0; j < 8; j++) {
            int col = n0 + tx*8 + j;
            float v = acc[i][j] + bias[col];
            int which = col / CC;
            int rem   = col - which*CC;
            int h = rem >> 6, d = rem & 63;
            float* dst = (which == 0) ? g_Q : (which == 1) ? g_K : g_V;
            dst[(((long)(b_*HH) + h)*NN + n_)*DD + d] = v;
        }
    }
}

// ---------------- cls row: Q2[b,h,0,:] = Q[b,h,0,:] * scale ------------------
__global__ void cls_scale()
{
    int idx = blockIdx.x * blockDim.x + threadIdx.x;
    if (idx >= BB*HH*DD) return;
    int bh = idx >> 6, d = idx & 63;
    g_Q2[(long)bh*NN*DD + d] = g_Q[(long)bh*NN*DD + d] * QSCALE;
}

// ---------------- stage C: q_patch = trans[h] @ Q[b,h,1:,:] * scale ----------
// per (b,h): [196x196] @ [196x64]; block: 64x64 out tile, 256 thr, 4x4/thread
__global__ __launch_bounds__(256) void qtrans_kernel()
{
    __shared__ float As[16][64];  // [k][q]
    __shared__ float Bs[16][64];  // [k][d]
    const int bh = blockIdx.y;
    const int q0 = blockIdx.x * 64;
    const int h  = bh % HH;
    const int t  = threadIdx.x;
    const int tx = t & 15, ty = t >> 4;
    float acc[4][4];
    #pragma unroll
    for (int i = 0; i < 4; i++)
        #pragma unroll
        for (int j = 0; j < 4; j++) acc[i][j] = 0.f;

    const float* tbase = g_TR + (long)h*LL*LL;
    const float* qbase = g_Q + ((long)bh*NN + 1)*DD;  // rows 1..196 by k index

    const int aq  = t >> 2;            // 0..63
    const int akb = (t & 3) * 4;       // 0..12
    const int bk  = t >> 4;            // 0..15
    const int bd  = (t & 15) * 4;      // 0..60

    for (int k0 = 0; k0 < LL; k0 += 16) {
        float4 av = make_float4(0,0,0,0);
        if (q0 + aq < LL) {
            const float* p = tbase + (long)(q0 + aq)*LL + k0 + akb;
            if (k0 + akb + 3 < LL) av = *(const float4*)p;
            else {
                float tmp[4] = {0,0,0,0};
                for (int j = 0; j < 4; j++) if (k0 + akb + j < LL) tmp[j] = p[j];
                av = make_float4(tmp[0], tmp[1], tmp[2], tmp[3]);
            }
        }
        As[akb+0][aq] = av.x; As[akb+1][aq] = av.y;
        As[akb+2][aq] = av.z; As[akb+3][aq] = av.w;

        float4 bv = make_float4(0,0,0,0);
        if (k0 + bk < LL) bv = *(const float4*)(qbase + (long)(k0 + bk)*DD + bd);
        *(float4*)&Bs[bk][bd] = bv;
        __syncthreads();
        #pragma unroll
        for (int kk = 0; kk < 16; kk++) {
            float a[4], bb[4];
            #pragma unroll
            for (int i = 0; i < 4; i++) a[i]  = As[kk][ty*4 + i];
            #pragma unroll
            for (int j = 0; j < 4; j++) bb[j] = Bs[kk][tx*4 + j];
            #pragma unroll
            for (int i = 0; i < 4; i++)
                #pragma unroll
                for (int j = 0; j < 4; j++) acc[i][j] += a[i] * bb[j];
        }
        __syncthreads();
    }
    #pragma unroll
    for (int i = 0; i < 4; i++) {
        int qg = q0 + ty*4 + i;
        if (qg >= LL) continue;
        #pragma unroll
        for (int j = 0; j < 4; j++)
            g_Q2[((long)bh*NN + 1 + qg)*DD + tx*4 + j] = acc[i][j] * QSCALE;
    }
}

// ---------------- stage D: attention per (b,h), 32 q rows per block ----------
__global__ __launch_bounds__(256) void attn_kernel()
{
    __shared__ float Qs[32][64];
    __shared__ float KVs[32][65];
    __shared__ float Ss[32][200];
    const int bh = blockIdx.y;
    const int b  = bh / HH, h = bh - b*HH;
    const int q0 = blockIdx.x * 32;
    const int t  = threadIdx.x;
    const float* qb = g_Q2 + (long)bh*NN*DD;
    const float* kb = g_K  + (long)bh*NN*DD;
    const float* vb = g_V  + (long)bh*NN*DD;

    const int lr = t >> 3;            // 0..31
    const int lc = (t & 7) * 8;       // 0..56
    {   // load Q tile
        float4 v0 = make_float4(0,0,0,0), v1 = v0;
        if (q0 + lr < NN) {
            const float* p = qb + (long)(q0 + lr)*DD + lc;
            v0 = *(const float4*)p; v1 = *(const float4*)(p + 4);
        }
        *(float4*)&Qs[lr][lc]     = v0;
        *(float4*)&Qs[lr][lc + 4] = v1;
    }

    const int kj  = t & 31;
    const int qib = t >> 5;           // 0..7
    for (int kt = 0; kt < 7; kt++) {
        int ks = kt * 32;
        int nk = (NN - ks < 32) ? (NN - ks) : 32;
        __syncthreads();
        {   // load K tile (zeros beyond seq end)
            float v[8] = {0,0,0,0,0,0,0,0};
            if (ks + lr < NN) {
                const float4 a = *(const float4*)(kb + (long)(ks + lr)*DD + lc);
                const float4 c = *(const float4*)(kb + (long)(ks + lr)*DD + lc + 4);
                v[0]=a.x; v[1]=a.y; v[2]=a.z; v[3]=a.w;
                v[4]=c.x; v[5]=c.y; v[6]=c.z; v[7]=c.w;
            }
            #pragma unroll
            for (int j = 0; j < 8; j++) KVs[lr][lc + j] = v[j];
        }
        __syncthreads();
        #pragma unroll
        for (int p = 0; p < 4; p++) {
            int qi = qib + p*8;
            float s = 0.f;
            #pragma unroll
            for (int d = 0; d < 64; d++) s += Qs[qi][d] * KVs[kj][d];
            if (kj < nk) Ss[qi][ks + kj] = s;
        }
    }
    __syncthreads();

    // softmax: 8 lanes per row
    {
        const int r  = t >> 3;
        const int l8 = t & 7;
        float mx = -1e30f;
        for (int c = l8; c < NN; c += 8) mx = fmaxf(mx, Ss[r][c]);
        #pragma unroll
        for (int o = 1; o < 8; o <<= 1) mx = fmaxf(mx, __shfl_xor_sync(0xffffffffu, mx, o));
        float sm = 0.f;
        for (int c = l8; c < NN; c += 8) { float e = __expf(Ss[r][c] - mx); Ss[r][c] = e; sm += e; }
        #pragma unroll
        for (int o = 1; o < 8; o <<= 1) sm += __shfl_xor_sync(0xffffffffu, sm, o);
        float inv = 1.f / sm;
        for (int c = l8; c < NN; c += 8) Ss[r][c] *= inv;
    }

    // O = P @ V
    const int d    = t & 63;
    const int qib2 = t >> 6;          // 0..3
    float o[8];
    #pragma unroll
    for (int p = 0; p < 8; p++) o[p] = 0.f;
    for (int kt = 0; kt < 7; kt++) {
        int ks = kt * 32;
        int nk = (NN - ks < 32) ? (NN - ks) : 32;
        __syncthreads();
        {   // load V tile
            float v[8] = {0,0,0,0,0,0,0,0};
            if (ks + lr < NN) {
                const float4 a = *(const float4*)(vb + (long)(ks + lr)*DD + lc);
                const float4 c = *(const float4*)(vb + (long)(ks + lr)*DD + lc + 4);
                v[0]=a.x; v[1]=a.y; v[2]=a.z; v[3]=a.w;
                v[4]=c.x; v[5]=c.y; v[6]=c.z; v[7]=c.w;
            }
            #pragma unroll
            for (int j = 0; j < 8; j++) KVs[lr][lc + j] = v[j];
        }
        __syncthreads();
        for (int kk = 0; kk < nk; kk++) {
            float vv = KVs[kk][d];
            #pragma unroll
            for (int p = 0; p < 8; p++) o[p] += Ss[qib2 + p*4][ks + kk] * vv;
        }
    }
    #pragma unroll
    for (int p = 0; p < 8; p++) {
        int qg = q0 + qib2 + p*4;
        if (qg < NN) g_ATT[((long)b*NN + qg)*CC + h*DD + d] = o[p];
    }
}

// ---------------- stage E: proj GEMM  (ATT[M,768] @ W[768,768] + b) ----------
__global__ __launch_bounds__(256) void gemm_proj(
    const float* __restrict__ Wt, const float* __restrict__ bias,
    float* __restrict__ Out)
{
    __shared__ float As[16][128];
    __shared__ float Bs[16][128];
    const int t  = threadIdx.x;
    const int tx = t & 15, ty = t >> 4;
    const int m0 = blockIdx.y * 128;
    const int n0 = blockIdx.x * 128;
    float acc[8][8];
    #pragma unroll
    for (int i = 0; i < 8; i++)
        #pragma unroll
        for (int j = 0; j < 8; j++) acc[i][j] = 0.f;

    const int arow = t >> 1;
    const int akb  = (t & 1) * 8;
    const int brow = t >> 4;
    const int bcol = (t & 15) * 8;

    for (int k0 = 0; k0 < CC; k0 += 16) {
        int gr = m0 + arow;
        float4 a0, a1;
        if (gr < MM) {
            const float* p = g_ATT + (long)gr*CC + k0 + akb;
            a0 = *(const float4*)p; a1 = *(const float4*)(p + 4);
        } else { a0 = make_float4(0,0,0,0); a1 = a0; }
        As[akb+0][arow]=a0.x; As[akb+1][arow]=a0.y; As[akb+2][arow]=a0.z; As[akb+3][arow]=a0.w;
        As[akb+4][arow]=a1.x; As[akb+5][arow]=a1.y; As[akb+6][arow]=a1.z; As[akb+7][arow]=a1.w;
        const float* qp = Wt + (long)(k0 + brow)*CC + n0 + bcol;
        float4 b0 = *(const float4*)qp;
        float4 b1 = *(const float4*)(qp + 4);
        *(float4*)&Bs[brow][bcol]   = b0;
        *(float4*)&Bs[brow][bcol+4] = b1;
        __syncthreads();
        #pragma unroll
        for (int kk = 0; kk < 16; kk++) {
            float a[8], bb[8];
            #pragma unroll
            for (int i = 0; i < 8; i++) a[i]  = As[kk][ty*8 + i];
            #pragma unroll
            for (int j = 0; j < 8; j++) bb[j] = Bs[kk][tx*8 + j];
            #pragma unroll
            for (int i = 0; i < 8; i++)
                #pragma unroll
                for (int j = 0; j < 8; j++) acc[i][j] += a[i] * bb[j];
        }
        __syncthreads();
    }
    #pragma unroll
    for (int i = 0; i < 8; i++) {
        int row = m0 + ty*8 + i;
        if (row >= MM) continue;
        #pragma unroll
        for (int j = 0; j < 8; j++) {
            int col = n0 + tx*8 + j;
            Out[(long)row*CC + col] = acc[i][j] + bias[col];
        }
    }
}

// ---------------- launch ------------------------------------------------------
extern "C" void kernel_launch(void* const* d_in, const int* in_sizes, int n_in,
                              void* d_out, int out_size)
{
    (void)in_sizes; (void)n_in; (void)out_size;
    const float* x      = (const float*)d_in[0];
    const float* qkv_w  = (const float*)d_in[1];
    const float* qkv_b  = (const float*)d_in[2];
    const float* proj_w = (const float*)d_in[3];
    const float* proj_b = (const float*)d_in[4];
    const float* table  = (const float*)d_in[5];
    const float* params = (const float*)d_in[6];
    float* out = (float*)d_out;

    trans_kernel<<<dim3(LL, 7), 256>>>(table, params);
    gemm_qkv<<<dim3(NC3/128, (MM + 127)/128), 256>>>(x, qkv_w, qkv_b);
    cls_scale<<<(BB*HH*DD + 255)/256, 256>>>();
    qtrans_kernel<<<dim3((LL + 63)/64, BB*HH), 256>>>();
    attn_kernel<<<dim3((NN + 31)/32, BB*HH), 256>>>();
    gemm_proj<<<dim3(CC/128, (MM + 127)/128), 256>>>(proj_w, proj_b, out);
}

// round 12
// speedup vs baseline: 1.0003x; 1.0003x over previous

#include <cuda_runtime.h>

#define BB 64
#define NN 197
#define CC 768
#define HH 12
#define DD 64
#define LL 196
#define WW 72
#define MM (BB*NN)        // 12608
#define NC3 (3*CC)        // 2304
#define QSCALE 0.125f     // D^-0.5

// ---------------- scratch (static device globals; no allocs allowed) ----------
__device__ float g_Q  [BB*HH*NN*DD];   // [b][h][n][d]
__device__ float g_K  [BB*HH*NN*DD];
__device__ float g_V  [BB*HH*NN*DD];
__device__ float g_Q2 [BB*HH*NN*DD];   // transformed+scaled q
__device__ float g_TR [HH*LL*LL];      // trans[h][q][k]
__device__ float g_ATT[MM*CC];         // attention out, [b][n][c]

// ---------------- stage A: trans[h][q][k] = table[q,k,:]@params[:,h] + eye ----
__global__ __launch_bounds__(256) void trans_kernel(
    const float* __restrict__ table, const float* __restrict__ params)
{
    __shared__ float Ps[WW*HH];     // params [w][h]
    __shared__ float Ts[32][WW];
    const int q  = blockIdx.x;
    const int k0 = blockIdx.y * 32;
    const int t  = threadIdx.x;
    for (int idx = t; idx < WW*HH; idx += 256) Ps[idx] = params[idx];
    for (int idx = t; idx < 32*WW; idx += 256) {
        int kk = idx / WW, w = idx - kk*WW;
        int kg = k0 + kk;
        Ts[kk][w] = (kg < LL) ? table[(q*LL + kg)*WW + w] : 0.f;
    }
    __syncthreads();
    for (int idx = t; idx < 32*HH; idx += 256) {
        int kk = idx / HH, h = idx - kk*HH;
        int kg = k0 + kk;
        if (kg >= LL) continue;
        float s = 0.f;
        #pragma unroll
        for (int w = 0; w < WW; w++) s += Ts[kk][w] * Ps[w*HH + h];
        if (q == kg) s += 1.f;
        g_TR[(h*LL + q)*LL + kg] = s;
    }
}

// ---------------- stage B: qkv GEMM  (X[M,768] @ W[768,2304] + b) -------------
// 128x128 block tile, 16 k-tile, 256 threads, 8x8 per-thread
__global__ __launch_bounds__(256) void gemm_qkv(
    const float* __restrict__ X, const float* __restrict__ Wt,
    const float* __restrict__ bias)
{
    __shared__ float As[16][128];  // [k][m]
    __shared__ float Bs[16][128];  // [k][n]
    const int t  = threadIdx.x;
    const int tx = t & 15, ty = t >> 4;
    const int m0 = blockIdx.y * 128;
    const int n0 = blockIdx.x * 128;
    float acc[8][8];
    #pragma unroll
    for (int i = 0; i < 8; i++)
        #pragma unroll
        for (int j = 0; j < 8; j++) acc[i][j] = 0.f;

    const int arow = t >> 1;           // 0..127
    const int akb  = (t & 1) * 8;      // 0 or 8
    const int brow = t >> 4;           // 0..15
    const int bcol = (t & 15) * 8;     // 0..120

    for (int k0 = 0; k0 < CC; k0 += 16) {
        int gr = m0 + arow;
        float4 a0, a1;
        if (gr < MM) {
            const float* p = X + (long)gr*CC + k0 + akb;
            a0 = *(const float4*)p; a1 = *(const float4*)(p + 4);
        } else { a0 = make_float4(0,0,0,0); a1 = a0; }
        As[akb+0][arow]=a0.x; As[akb+1][arow]=a0.y; As[akb+2][arow]=a0.z; As[akb+3][arow]=a0.w;
        As[akb+4][arow]=a1.x; As[akb+5][arow]=a1.y; As[akb+6][arow]=a1.z; As[akb+7][arow]=a1.w;
        const float* qp = Wt + (long)(k0 + brow)*NC3 + n0 + bcol;
        float4 b0 = *(const float4*)qp;
        float4 b1 = *(const float4*)(qp + 4);
        *(float4*)&Bs[brow][bcol]   = b0;
        *(float4*)&Bs[brow][bcol+4] = b1;
        __syncthreads();
        #pragma unroll
        for (int kk = 0; kk < 16; kk++) {
            float a[8], bb[8];
            #pragma unroll
            for (int i = 0; i < 8; i++) a[i]  = As[kk][ty*8 + i];
            #pragma unroll
            for (int j = 0; j < 8; j++) bb[j] = Bs[kk][tx*8 + j];
            #pragma unroll
            for (int i = 0; i < 8; i++)
                #pragma unroll
                for (int j = 0; j < 8; j++) acc[i][j] += a[i] * bb[j];
        }
        __syncthreads();
    }
    // epilogue: scatter to Q/K/V [b][h][n][d]
    #pragma unroll
    for (int i = 0; i < 8; i++) {
        int row = m0 + ty*8 + i;
        if (row >= MM) continue;
        int b_ = row / NN, n_ = row - b_*NN;
        #pragma unroll
        for (int j = 0; j < 8; j++) {
            int col = n0 + tx*8 + j;
            float v = acc[i][j] + bias[col];
            int which = col / CC;
            int rem   = col - which*CC;
            int h = rem >> 6, d = rem & 63;
            float* dst = (which == 0) ? g_Q : (which == 1) ? g_K : g_V;
            dst[(((long)(b_*HH) + h)*NN + n_)*DD + d] = v;
        }
    }
}

// ---------------- cls row: Q2[b,h,0,:] = Q[b,h,0,:] * scale ------------------
__global__ void cls_scale()
{
    int idx = blockIdx.x * blockDim.x + threadIdx.x;
    if (idx >= BB*HH*DD) return;
    int bh = idx >> 6, d = idx & 63;
    g_Q2[(long)bh*NN*DD + d] = g_Q[(long)bh*NN*DD + d] * QSCALE;
}

// ---------------- stage C: q_patch = trans[h] @ Q[b,h,1:,:] * scale ----------
// per (b,h): [196x196] @ [196x64]; block: 64x64 out tile, 256 thr, 4x4/thread
__global__ __launch_bounds__(256) void qtrans_kernel()
{
    __shared__ float As[16][64];  // [k][q]
    __shared__ float Bs[16][64];  // [k][d]
    const int bh = blockIdx.y;
    const int q0 = blockIdx.x * 64;
    const int h  = bh % HH;
    const int t  = threadIdx.x;
    const int tx = t & 15, ty = t >> 4;
    float acc[4][4];
    #pragma unroll
    for (int i = 0; i < 4; i++)
        #pragma unroll
        for (int j = 0; j < 4; j++) acc[i][j] = 0.f;

    const float* tbase = g_TR + (long)h*LL*LL;
    const float* qbase = g_Q + ((long)bh*NN + 1)*DD;  // rows 1..196 by k index

    const int aq  = t >> 2;            // 0..63
    const int akb = (t & 3) * 4;       // 0..12
    const int bk  = t >> 4;            // 0..15
    const int bd  = (t & 15) * 4;      // 0..60

    for (int k0 = 0; k0 < LL; k0 += 16) {
        float4 av = make_float4(0,0,0,0);
        if (q0 + aq < LL) {
            const float* p = tbase + (long)(q0 + aq)*LL + k0 + akb;
            if (k0 + akb + 3 < LL) av = *(const float4*)p;
            else {
                float tmp[4] = {0,0,0,0};
                for (int j = 0; j < 4; j++) if (k0 + akb + j < LL) tmp[j] = p[j];
                av = make_float4(tmp[0], tmp[1], tmp[2], tmp[3]);
            }
        }
        As[akb+0][aq] = av.x; As[akb+1][aq] = av.y;
        As[akb+2][aq] = av.z; As[akb+3][aq] = av.w;

        float4 bv = make_float4(0,0,0,0);
        if (k0 + bk < LL) bv = *(const float4*)(qbase + (long)(k0 + bk)*DD + bd);
        *(float4*)&Bs[bk][bd] = bv;
        __syncthreads();
        #pragma unroll
        for (int kk = 0; kk < 16; kk++) {
            float a[4], bb[4];
            #pragma unroll
            for (int i = 0; i < 4; i++) a[i]  = As[kk][ty*4 + i];
            #pragma unroll
            for (int j = 0; j < 4; j++) bb[j] = Bs[kk][tx*4 + j];
            #pragma unroll
            for (int i = 0; i < 4; i++)
                #pragma unroll
                for (int j = 0; j < 4; j++) acc[i][j] += a[i] * bb[j];
        }
        __syncthreads();
    }
    #pragma unroll
    for (int i = 0; i < 4; i++) {
        int qg = q0 + ty*4 + i;
        if (qg >= LL) continue;
        #pragma unroll
        for (int j = 0; j < 4; j++)
            g_Q2[((long)bh*NN + 1 + qg)*DD + tx*4 + j] = acc[i][j] * QSCALE;
    }
}

// ---------------- stage D: attention per (b,h), 32 q rows per block ----------
__global__ __launch_bounds__(256) void attn_kernel()
{
    __shared__ float Qs[32][64];
    __shared__ float KVs[32][65];
    __shared__ float Ss[32][200];
    const int bh = blockIdx.y;
    const int b  = bh / HH, h = bh - b*HH;
    const int q0 = blockIdx.x * 32;
    const int t  = threadIdx.x;
    const float* qb = g_Q2 + (long)bh*NN*DD;
    const float* kb = g_K  + (long)bh*NN*DD;
    const float* vb = g_V  + (long)bh*NN*DD;

    const int lr = t >> 3;            // 0..31
    const int lc = (t & 7) * 8;       // 0..56
    {   // load Q tile
        float4 v0 = make_float4(0,0,0,0), v1 = v0;
        if (q0 + lr < NN) {
            const float* p = qb + (long)(q0 + lr)*DD + lc;
            v0 = *(const float4*)p; v1 = *(const float4*)(p + 4);
        }
        *(float4*)&Qs[lr][lc]     = v0;
        *(float4*)&Qs[lr][lc + 4] = v1;
    }

    const int kj  = t & 31;
    const int qib = t >> 5;           // 0..7
    for (int kt = 0; kt < 7; kt++) {
        int ks = kt * 32;
        int nk = (NN - ks < 32) ? (NN - ks) : 32;
        __syncthreads();
        {   // load K tile (zeros beyond seq end)
            float v[8] = {0,0,0,0,0,0,0,0};
            if (ks + lr < NN) {
                const float4 a = *(const float4*)(kb + (long)(ks + lr)*DD + lc);
                const float4 c = *(const float4*)(kb + (long)(ks + lr)*DD + lc + 4);
                v[0]=a.x; v[1]=a.y; v[2]=a.z; v[3]=a.w;
                v[4]=c.x; v[5]=c.y; v[6]=c.z; v[7]=c.w;
            }
            #pragma unroll
            for (int j = 0; j < 8; j++) KVs[lr][lc + j] = v[j];
        }
        __syncthreads();
        #pragma unroll
        for (int p = 0; p < 4; p++) {
            int qi = qib + p*8;
            float s = 0.f;
            #pragma unroll
            for (int d = 0; d < 64; d++) s += Qs[qi][d] * KVs[kj][d];
            if (kj < nk) Ss[qi][ks + kj] = s;
        }
    }
    __syncthreads();

    // softmax: 8 lanes per row
    {
        const int r  = t >> 3;
        const int l8 = t & 7;
        float mx = -1e30f;
        for (int c = l8; c < NN; c += 8) mx = fmaxf(mx, Ss[r][c]);
        #pragma unroll
        for (int o = 1; o < 8; o <<= 1) mx = fmaxf(mx, __shfl_xor_sync(0xffffffffu, mx, o));
        float sm = 0.f;
        for (int c = l8; c < NN; c += 8) { float e = __expf(Ss[r][c] - mx); Ss[r][c] = e; sm += e; }
        #pragma unroll
        for (int o = 1; o < 8; o <<= 1) sm += __shfl_xor_sync(0xffffffffu, sm, o);
        float inv = 1.f / sm;
        for (int c = l8; c < NN; c += 8) Ss[r][c] *= inv;
    }

    // O = P @ V
    const int d    = t & 63;
    const int qib2 = t >> 6;          // 0..3
    float o[8];
    #pragma unroll
    for (int p = 0; p < 8; p++) o[p] = 0.f;
    for (int kt = 0; kt < 7; kt++) {
        int ks = kt * 32;
        int nk = (NN - ks < 32) ? (NN - ks) : 32;
        __syncthreads();
        {   // load V tile
            float v[8] = {0,0,0,0,0,0,0,0};
            if (ks + lr < NN) {
                const float4 a = *(const float4*)(vb + (long)(ks + lr)*DD + lc);
                const float4 c = *(const float4*)(vb + (long)(ks + lr)*DD + lc + 4);
                v[0]=a.x; v[1]=a.y; v[2]=a.z; v[3]=a.w;
                v[4]=c.x; v[5]=c.y; v[6]=c.z; v[7]=c.w;
            }
            #pragma unroll
            for (int j = 0; j < 8; j++) KVs[lr][lc + j] = v[j];
        }
        __syncthreads();
        for (int kk = 0; kk < nk; kk++) {
            float vv = KVs[kk][d];
            #pragma unroll
            for (int p = 0; p < 8; p++) o[p] += Ss[qib2 + p*4][ks + kk] * vv;
        }
    }
    #pragma unroll
    for (int p = 0; p < 8; p++) {
        int qg = q0 + qib2 + p*4;
        if (qg < NN) g_ATT[((long)b*NN + qg)*CC + h*DD + d] = o[p];
    }
}

// ---------------- stage E: proj GEMM  (ATT[M,768] @ W[768,768] + b) ----------
__global__ __launch_bounds__(256) void gemm_proj(
    const float* __restrict__ Wt, const float* __restrict__ bias,
    float* __restrict__ Out)
{
    __shared__ float As[16][128];
    __shared__ float Bs[16][128];
    const int t  = threadIdx.x;
    const int tx = t & 15, ty = t >> 4;
    const int m0 = blockIdx.y * 128;
    const int n0 = blockIdx.x * 128;
    float acc[8][8];
    #pragma unroll
    for (int i = 0; i < 8; i++)
        #pragma unroll
        for (int j = 0; j < 8; j++) acc[i][j] = 0.f;

    const int arow = t >> 1;
    const int akb  = (t & 1) * 8;
    const int brow = t >> 4;
    const int bcol = (t & 15) * 8;

    for (int k0 = 0; k0 < CC; k0 += 16) {
        int gr = m0 + arow;
        float4 a0, a1;
        if (gr < MM) {
            const float* p = g_ATT + (long)gr*CC + k0 + akb;
            a0 = *(const float4*)p; a1 = *(const float4*)(p + 4);
        } else { a0 = make_float4(0,0,0,0); a1 = a0; }
        As[akb+0][arow]=a0.x; As[akb+1][arow]=a0.y; As[akb+2][arow]=a0.z; As[akb+3][arow]=a0.w;
        As[akb+4][arow]=a1.x; As[akb+5][arow]=a1.y; As[akb+6][arow]=a1.z; As[akb+7][arow]=a1.w;
        const float* qp = Wt + (long)(k0 + brow)*CC + n0 + bcol;
        float4 b0 = *(const float4*)qp;
        float4 b1 = *(const float4*)(qp + 4);
        *(float4*)&Bs[brow][bcol]   = b0;
        *(float4*)&Bs[brow][bcol+4] = b1;
        __syncthreads();
        #pragma unroll
        for (int kk = 0; kk < 16; kk++) {
            float a[8], bb[8];
            #pragma unroll
            for (int i = 0; i < 8; i++) a[i]  = As[kk][ty*8 + i];
            #pragma unroll
            for (int j = 0; j < 8; j++) bb[j] = Bs[kk][tx*8 + j];
            #pragma unroll
            for (int i = 0; i < 8; i++)
                #pragma unroll
                for (int j = 0; j < 8; j++) acc[i][j] += a[i] * bb[j];
        }
        __syncthreads();
    }
    #pragma unroll
    for (int i = 0; i < 8; i++) {
        int row = m0 + ty*8 + i;
        if (row >= MM) continue;
        #pragma unroll
        for (int j = 0; j < 8; j++) {
            int col = n0 + tx*8 + j;
            Out[(long)row*CC + col] = acc[i][j] + bias[col];
        }
    }
}

// ---------------- launch ------------------------------------------------------
extern "C" void kernel_launch(void* const* d_in, const int* in_sizes, int n_in,
                              void* d_out, int out_size)
{
    (void)in_sizes; (void)n_in; (void)out_size;
    const float* x      = (const float*)d_in[0];
    const float* qkv_w  = (const float*)d_in[1];
    const float* qkv_b  = (const float*)d_in[2];
    const float* proj_w = (const float*)d_in[3];
    const float* proj_b = (const float*)d_in[4];
    const float* table  = (const float*)d_in[5];
    const float* params = (const float*)d_in[6];
    float* out = (float*)d_out;

    trans_kernel<<<dim3(LL, 7), 256>>>(table, params);
    gemm_qkv<<<dim3(NC3/128, (MM + 127)/128), 256>>>(x, qkv_w, qkv_b);
    cls_scale<<<(BB*HH*DD + 255)/256, 256>>>();
    qtrans_kernel<<<dim3((LL + 63)/64, BB*HH), 256>>>();
    attn_kernel<<<dim3((NN + 31)/32, BB*HH), 256>>>();
    gemm_proj<<<dim3(CC/128, (MM + 127)/128), 256>>>(proj_w, proj_b, out);
}

// round 13
// speedup vs baseline: 1.0424x; 1.0421x over previous

#include <cuda_runtime.h>

#define BB 64
#define NN 197
#define CC 768
#define HH 12
#define DD 64
#define LL 196
#define WW 72
#define MM (BB*NN)        // 12608
#define NC3 (3*CC)        // 2304
#define QSCALE 0.125f     // D^-0.5

// ---------------- scratch (static device globals; no allocs allowed) ----------
__device__ float g_Q  [BB*HH*NN*DD];   // [b][h][n][d]
__device__ float g_K  [BB*HH*NN*DD];
__device__ float g_V  [BB*HH*NN*DD];
__device__ float g_Q2 [BB*HH*NN*DD];   // transformed+scaled q
__device__ float g_TR [HH*LL*LL];      // trans[h][q][k]
__device__ float g_ATT[MM*CC];         // attention out, [b][n][c]

// ---------------- stage A: trans[h][q][k] = table[q,k,:]@params[:,h] + eye ----
__global__ __launch_bounds__(256) void trans_kernel(
    const float* __restrict__ table, const float* __restrict__ params)
{
    __shared__ float Ps[WW*HH];     // params [w][h]
    __shared__ float Ts[32][WW];
    const int q  = blockIdx.x;
    const int k0 = blockIdx.y * 32;
    const int t  = threadIdx.x;
    for (int idx = t; idx < WW*HH; idx += 256) Ps[idx] = params[idx];
    for (int idx = t; idx < 32*WW; idx += 256) {
        int kk = idx / WW, w = idx - kk*WW;
        int kg = k0 + kk;
        Ts[kk][w] = (kg < LL) ? table[(q*LL + kg)*WW + w] : 0.f;
    }
    __syncthreads();
    for (int idx = t; idx < 32*HH; idx += 256) {
        int kk = idx / HH, h = idx - kk*HH;
        int kg = k0 + kk;
        if (kg >= LL) continue;
        float s = 0.f;
        #pragma unroll
        for (int w = 0; w < WW; w++) s += Ts[kk][w] * Ps[w*HH + h];
        if (q == kg) s += 1.f;
        g_TR[(h*LL + q)*LL + kg] = s;
    }
}

// ---------------- stage B: qkv GEMM  (X[M,768] @ W[768,2304] + b) -------------
// 128x128 block tile, 32 k-tile, 256 threads, 8x8 per-thread
__global__ __launch_bounds__(256) void gemm_qkv(
    const float* __restrict__ X, const float* __restrict__ Wt,
    const float* __restrict__ bias)
{
    __shared__ float As[32][128];  // [k][m]
    __shared__ float Bs[32][128];  // [k][n]
    const int t  = threadIdx.x;
    const int tx = t & 15, ty = t >> 4;
    const int m0 = blockIdx.y * 128;
    const int n0 = blockIdx.x * 128;
    float acc[8][8];
    #pragma unroll
    for (int i = 0; i < 8; i++)
        #pragma unroll
        for (int j = 0; j < 8; j++) acc[i][j] = 0.f;

    const int arow = t >> 1;           // 0..127
    const int akb  = (t & 1) * 8;      // 0 or 8   (k segments akb, akb+16)
    const int brow = t >> 4;           // 0..15    (rows brow, brow+16)
    const int bcol = (t & 15) * 8;     // 0..120

    for (int k0 = 0; k0 < CC; k0 += 32) {
        int gr = m0 + arow;
        // A segment 1: k = k0+akb .. +7
        float4 a0, a1;
        if (gr < MM) {
            const float* p = X + (long)gr*CC + k0 + akb;
            a0 = *(const float4*)p; a1 = *(const float4*)(p + 4);
        } else { a0 = make_float4(0,0,0,0); a1 = a0; }
        As[akb+0][arow]=a0.x; As[akb+1][arow]=a0.y; As[akb+2][arow]=a0.z; As[akb+3][arow]=a0.w;
        As[akb+4][arow]=a1.x; As[akb+5][arow]=a1.y; As[akb+6][arow]=a1.z; As[akb+7][arow]=a1.w;
        // A segment 2: k = k0+16+akb .. +7
        if (gr < MM) {
            const float* p = X + (long)gr*CC + k0 + 16 + akb;
            a0 = *(const float4*)p; a1 = *(const float4*)(p + 4);
        } else { a0 = make_float4(0,0,0,0); a1 = a0; }
        As[16+akb+0][arow]=a0.x; As[16+akb+1][arow]=a0.y; As[16+akb+2][arow]=a0.z; As[16+akb+3][arow]=a0.w;
        As[16+akb+4][arow]=a1.x; As[16+akb+5][arow]=a1.y; As[16+akb+6][arow]=a1.z; As[16+akb+7][arow]=a1.w;
        // B rows brow and brow+16
        const float* qp = Wt + (long)(k0 + brow)*NC3 + n0 + bcol;
        float4 b0 = *(const float4*)qp;
        float4 b1 = *(const float4*)(qp + 4);
        *(float4*)&Bs[brow][bcol]   = b0;
        *(float4*)&Bs[brow][bcol+4] = b1;
        const float* qp2 = Wt + (long)(k0 + 16 + brow)*NC3 + n0 + bcol;
        b0 = *(const float4*)qp2;
        b1 = *(const float4*)(qp2 + 4);
        *(float4*)&Bs[brow+16][bcol]   = b0;
        *(float4*)&Bs[brow+16][bcol+4] = b1;
        __syncthreads();
        #pragma unroll
        for (int kk = 0; kk < 32; kk++) {
            float a[8], bb[8];
            #pragma unroll
            for (int i = 0; i < 8; i++) a[i]  = As[kk][ty*8 + i];
            #pragma unroll
            for (int j = 0; j < 8; j++) bb[j] = Bs[kk][tx*8 + j];
            #pragma unroll
            for (int i = 0; i < 8; i++)
                #pragma unroll
                for (int j = 0; j < 8; j++) acc[i][j] += a[i] * bb[j];
        }
        __syncthreads();
    }
    // epilogue: scatter to Q/K/V [b][h][n][d]
    #pragma unroll
    for (int i = 0; i < 8; i++) {
        int row = m0 + ty*8 + i;
        if (row >= MM) continue;
        int b_ = row / NN, n_ = row - b_*NN;
        #pragma unroll
        for (int j = 0; j < 8; j++) {
            int col = n0 + tx*8 + j;
            float v = acc[i][j] + bias[col];
            int which = col / CC;
            int rem   = col - which*CC;
            int h = rem >> 6, d = rem & 63;
            float* dst = (which == 0) ? g_Q : (which == 1) ? g_K : g_V;
            dst[(((long)(b_*HH) + h)*NN + n_)*DD + d] = v;
        }
    }
}

// ---------------- cls row: Q2[b,h,0,:] = Q[b,h,0,:] * scale ------------------
__global__ void cls_scale()
{
    int idx = blockIdx.x * blockDim.x + threadIdx.x;
    if (idx >= BB*HH*DD) return;
    int bh = idx >> 6, d = idx & 63;
    g_Q2[(long)bh*NN*DD + d] = g_Q[(long)bh*NN*DD + d] * QSCALE;
}

// ---------------- stage C: q_patch = trans[h] @ Q[b,h,1:,:] * scale ----------
// per (b,h): [196x196] @ [196x64]; block: 64x64 out tile, 256 thr, 4x4/thread
__global__ __launch_bounds__(256) void qtrans_kernel()
{
    __shared__ float As[16][64];  // [k][q]
    __shared__ float Bs[16][64];  // [k][d]
    const int bh = blockIdx.y;
    const int q0 = blockIdx.x * 64;
    const int h  = bh % HH;
    const int t  = threadIdx.x;
    const int tx = t & 15, ty = t >> 4;
    float acc[4][4];
    #pragma unroll
    for (int i = 0; i < 4; i++)
        #pragma unroll
        for (int j = 0; j < 4; j++) acc[i][j] = 0.f;

    const float* tbase = g_TR + (long)h*LL*LL;
    const float* qbase = g_Q + ((long)bh*NN + 1)*DD;  // rows 1..196 by k index

    const int aq  = t >> 2;            // 0..63
    const int akb = (t & 3) * 4;       // 0..12
    const int bk  = t >> 4;            // 0..15
    const int bd  = (t & 15) * 4;      // 0..60

    for (int k0 = 0; k0 < LL; k0 += 16) {
        float4 av = make_float4(0,0,0,0);
        if (q0 + aq < LL) {
            const float* p = tbase + (long)(q0 + aq)*LL + k0 + akb;
            if (k0 + akb + 3 < LL) av = *(const float4*)p;
            else {
                float tmp[4] = {0,0,0,0};
                for (int j = 0; j < 4; j++) if (k0 + akb + j < LL) tmp[j] = p[j];
                av = make_float4(tmp[0], tmp[1], tmp[2], tmp[3]);
            }
        }
        As[akb+0][aq] = av.x; As[akb+1][aq] = av.y;
        As[akb+2][aq] = av.z; As[akb+3][aq] = av.w;

        float4 bv = make_float4(0,0,0,0);
        if (k0 + bk < LL) bv = *(const float4*)(qbase + (long)(k0 + bk)*DD + bd);
        *(float4*)&Bs[bk][bd] = bv;
        __syncthreads();
        #pragma unroll
        for (int kk = 0; kk < 16; kk++) {
            float a[4], bb[4];
            #pragma unroll
            for (int i = 0; i < 4; i++) a[i]  = As[kk][ty*4 + i];
            #pragma unroll
            for (int j = 0; j < 4; j++) bb[j] = Bs[kk][tx*4 + j];
            #pragma unroll
            for (int i = 0; i < 4; i++)
                #pragma unroll
                for (int j = 0; j < 4; j++) acc[i][j] += a[i] * bb[j];
        }
        __syncthreads();
    }
    #pragma unroll
    for (int i = 0; i < 4; i++) {
        int qg = q0 + ty*4 + i;
        if (qg >= LL) continue;
        #pragma unroll
        for (int j = 0; j < 4; j++)
            g_Q2[((long)bh*NN + 1 + qg)*DD + tx*4 + j] = acc[i][j] * QSCALE;
    }
}

// ---------------- stage D: attention per (b,h), 32 q rows per block ----------
__global__ __launch_bounds__(256) void attn_kernel()
{
    __shared__ float Qs[32][64];
    __shared__ float KVs[32][68];   // stride 68 floats: 16B-aligned rows, bank-clean
    __shared__ float Ss[32][200];
    const int bh = blockIdx.y;
    const int b  = bh / HH, h = bh - b*HH;
    const int q0 = blockIdx.x * 32;
    const int t  = threadIdx.x;
    const float* qb = g_Q2 + (long)bh*NN*DD;
    const float* kb = g_K  + (long)bh*NN*DD;
    const float* vb = g_V  + (long)bh*NN*DD;

    const int lr = t >> 3;            // 0..31
    const int lc = (t & 7) * 8;       // 0..56
    {   // load Q tile
        float4 v0 = make_float4(0,0,0,0), v1 = v0;
        if (q0 + lr < NN) {
            const float* p = qb + (long)(q0 + lr)*DD + lc;
            v0 = *(const float4*)p; v1 = *(const float4*)(p + 4);
        }
        *(float4*)&Qs[lr][lc]     = v0;
        *(float4*)&Qs[lr][lc + 4] = v1;
    }

    const int kj  = t & 31;
    const int qib = t >> 5;           // 0..7
    for (int kt = 0; kt < 7; kt++) {
        int ks = kt * 32;
        int nk = (NN - ks < 32) ? (NN - ks) : 32;
        __syncthreads();
        {   // load K tile (zeros beyond seq end)
            float v[8] = {0,0,0,0,0,0,0,0};
            if (ks + lr < NN) {
                const float4 a = *(const float4*)(kb + (long)(ks + lr)*DD + lc);
                const float4 c = *(const float4*)(kb + (long)(ks + lr)*DD + lc + 4);
                v[0]=a.x; v[1]=a.y; v[2]=a.z; v[3]=a.w;
                v[4]=c.x; v[5]=c.y; v[6]=c.z; v[7]=c.w;
            }
            #pragma unroll
            for (int j = 0; j < 8; j++) KVs[lr][lc + j] = v[j];
        }
        __syncthreads();
        // S = Q @ K^T : 4 q-rows per thread, float4 over d (5 LDS.128 / 16 FFMA)
        {
            float s0 = 0.f, s1 = 0.f, s2 = 0.f, s3 = 0.f;
            #pragma unroll
            for (int d0 = 0; d0 < 64; d0 += 4) {
                const float4 kv = *(const float4*)&KVs[kj][d0];
                const float4 qa = *(const float4*)&Qs[qib     ][d0];
                const float4 qc = *(const float4*)&Qs[qib +  8][d0];
                const float4 qe = *(const float4*)&Qs[qib + 16][d0];
                const float4 qg = *(const float4*)&Qs[qib + 24][d0];
                s0 += qa.x*kv.x + qa.y*kv.y + qa.z*kv.z + qa.w*kv.w;
                s1 += qc.x*kv.x + qc.y*kv.y + qc.z*kv.z + qc.w*kv.w;
                s2 += qe.x*kv.x + qe.y*kv.y + qe.z*kv.z + qe.w*kv.w;
                s3 += qg.x*kv.x + qg.y*kv.y + qg.z*kv.z + qg.w*kv.w;
            }
            if (kj < nk) {
                Ss[qib     ][ks + kj] = s0;
                Ss[qib +  8][ks + kj] = s1;
                Ss[qib + 16][ks + kj] = s2;
                Ss[qib + 24][ks + kj] = s3;
            }
        }
    }
    __syncthreads();

    // softmax: 8 lanes per row
    {
        const int r  = t >> 3;
        const int l8 = t & 7;
        float mx = -1e30f;
        for (int c = l8; c < NN; c += 8) mx = fmaxf(mx, Ss[r][c]);
        #pragma unroll
        for (int o = 1; o < 8; o <<= 1) mx = fmaxf(mx, __shfl_xor_sync(0xffffffffu, mx, o));
        float sm = 0.f;
        for (int c = l8; c < NN; c += 8) { float e = __expf(Ss[r][c] - mx); Ss[r][c] = e; sm += e; }
        #pragma unroll
        for (int o = 1; o < 8; o <<= 1) sm += __shfl_xor_sync(0xffffffffu, sm, o);
        float inv = 1.f / sm;
        for (int c = l8; c < NN; c += 8) Ss[r][c] *= inv;
    }

    // O = P @ V
    const int d    = t & 63;
    const int qib2 = t >> 6;          // 0..3
    float o[8];
    #pragma unroll
    for (int p = 0; p < 8; p++) o[p] = 0.f;
    for (int kt = 0; kt < 7; kt++) {
        int ks = kt * 32;
        int nk = (NN - ks < 32) ? (NN - ks) : 32;
        __syncthreads();
        {   // load V tile
            float v[8] = {0,0,0,0,0,0,0,0};
            if (ks + lr < NN) {
                const float4 a = *(const float4*)(vb + (long)(ks + lr)*DD + lc);
                const float4 c = *(const float4*)(vb + (long)(ks + lr)*DD + lc + 4);
                v[0]=a.x; v[1]=a.y; v[2]=a.z; v[3]=a.w;
                v[4]=c.x; v[5]=c.y; v[6]=c.z; v[7]=c.w;
            }
            #pragma unroll
            for (int j = 0; j < 8; j++) KVs[lr][lc + j] = v[j];
        }
        __syncthreads();
        for (int kk = 0; kk < nk; kk++) {
            float vv = KVs[kk][d];
            #pragma unroll
            for (int p = 0; p < 8; p++) o[p] += Ss[qib2 + p*4][ks + kk] * vv;
        }
    }
    #pragma unroll
    for (int p = 0; p < 8; p++) {
        int qg = q0 + qib2 + p*4;
        if (qg < NN) g_ATT[((long)b*NN + qg)*CC + h*DD + d] = o[p];
    }
}

// ---------------- stage E: proj GEMM  (ATT[M,768] @ W[768,768] + b) ----------
__global__ __launch_bounds__(256) void gemm_proj(
    const float* __restrict__ Wt, const float* __restrict__ bias,
    float* __restrict__ Out)
{
    __shared__ float As[32][128];
    __shared__ float Bs[32][128];
    const int t  = threadIdx.x;
    const int tx = t & 15, ty = t >> 4;
    const int m0 = blockIdx.y * 128;
    const int n0 = blockIdx.x * 128;
    float acc[8][8];
    #pragma unroll
    for (int i = 0; i < 8; i++)
        #pragma unroll
        for (int j = 0; j < 8; j++) acc[i][j] = 0.f;

    const int arow = t >> 1;
    const int akb  = (t & 1) * 8;
    const int brow = t >> 4;
    const int bcol = (t & 15) * 8;

    for (int k0 = 0; k0 < CC; k0 += 32) {
        int gr = m0 + arow;
        float4 a0, a1;
        if (gr < MM) {
            const float* p = g_ATT + (long)gr*CC + k0 + akb;
            a0 = *(const float4*)p; a1 = *(const float4*)(p + 4);
        } else { a0 = make_float4(0,0,0,0); a1 = a0; }
        As[akb+0][arow]=a0.x; As[akb+1][arow]=a0.y; As[akb+2][arow]=a0.z; As[akb+3][arow]=a0.w;
        As[akb+4][arow]=a1.x; As[akb+5][arow]=a1.y; As[akb+6][arow]=a1.z; As[akb+7][arow]=a1.w;
        if (gr < MM) {
            const float* p = g_ATT + (long)gr*CC + k0 + 16 + akb;
            a0 = *(const float4*)p; a1 = *(const float4*)(p + 4);
        } else { a0 = make_float4(0,0,0,0); a1 = a0; }
        As[16+akb+0][arow]=a0.x; As[16+akb+1][arow]=a0.y; As[16+akb+2][arow]=a0.z; As[16+akb+3][arow]=a0.w;
        As[16+akb+4][arow]=a1.x; As[16+akb+5][arow]=a1.y; As[16+akb+6][arow]=a1.z; As[16+akb+7][arow]=a1.w;
        const float* qp = Wt + (long)(k0 + brow)*CC + n0 + bcol;
        float4 b0 = *(const float4*)qp;
        float4 b1 = *(const float4*)(qp + 4);
        *(float4*)&Bs[brow][bcol]   = b0;
        *(float4*)&Bs[brow][bcol+4] = b1;
        const float* qp2 = Wt + (long)(k0 + 16 + brow)*CC + n0 + bcol;
        b0 = *(const float4*)qp2;
        b1 = *(const float4*)(qp2 + 4);
        *(float4*)&Bs[brow+16][bcol]   = b0;
        *(float4*)&Bs[brow+16][bcol+4] = b1;
        __syncthreads();
        #pragma unroll
        for (int kk = 0; kk < 32; kk++) {
            float a[8], bb[8];
            #pragma unroll
            for (int i = 0; i < 8; i++) a[i]  = As[kk][ty*8 + i];
            #pragma unroll
            for (int j = 0; j < 8; j++) bb[j] = Bs[kk][tx*8 + j];
            #pragma unroll
            for (int i = 0; i < 8; i++)
                #pragma unroll
                for (int j = 0; j < 8; j++) acc[i][j] += a[i] * bb[j];
        }
        __syncthreads();
    }
    #pragma unroll
    for (int i = 0; i < 8; i++) {
        int row = m0 + ty*8 + i;
        if (row >= MM) continue;
        #pragma unroll
        for (int j = 0; j < 8; j++) {
            int col = n0 + tx*8 + j;
            Out[(long)row*CC + col] = acc[i][j] + bias[col];
        }
    }
}

// ---------------- launch ------------------------------------------------------
extern "C" void kernel_launch(void* const* d_in, const int* in_sizes, int n_in,
                              void* d_out, int out_size)
{
    (void)in_sizes; (void)n_in; (void)out_size;
    const float* x      = (const float*)d_in[0];
    const float* qkv_w  = (const float*)d_in[1];
    const float* qkv_b  = (const float*)d_in[2];
    const float* proj_w = (const float*)d_in[3];
    const float* proj_b = (const float*)d_in[4];
    const float* table  = (const float*)d_in[5];
    const float* params = (const float*)d_in[6];
    float* out = (float*)d_out;

    trans_kernel<<<dim3(LL, 7), 256>>>(table, params);
    gemm_qkv<<<dim3(NC3/128, (MM + 127)/128), 256>>>(x, qkv_w, qkv_b);
    cls_scale<<<(BB*HH*DD + 255)/256, 256>>>();
    qtrans_kernel<<<dim3((LL + 63)/64, BB*HH), 256>>>();
    attn_kernel<<<dim3((NN + 31)/32, BB*HH), 256>>>();
    gemm_proj<<<dim3(CC/128, (MM + 127)/128), 256>>>(proj_w, proj_b, out);
}

// round 14
// speedup vs baseline: 1.0618x; 1.0186x over previous

#include <cuda_runtime.h>

#define BB 64
#define NN 197
#define CC 768
#define HH 12
#define DD 64
#define LL 196
#define WW 72
#define MM (BB*NN)        // 12608
#define NC3 (3*CC)        // 2304
#define QSCALE 0.125f     // D^-0.5

// ---------------- scratch (static device globals; no allocs allowed) ----------
__device__ float g_Q  [BB*HH*NN*DD];   // [b][h][n][d]
__device__ float g_K  [BB*HH*NN*DD];
__device__ float g_V  [BB*HH*NN*DD];
__device__ float g_Q2 [BB*HH*NN*DD];   // transformed+scaled q
__device__ float g_TR [HH*LL*LL];      // trans[h][q][k]
__device__ float g_ATT[MM*CC];         // attention out, [b][n][c]

// ---------------- stage A: trans[h][q][k] = table[q,k,:]@params[:,h] + eye ----
__global__ __launch_bounds__(256) void trans_kernel(
    const float* __restrict__ table, const float* __restrict__ params)
{
    __shared__ float Ps[WW*HH];     // params [w][h]
    __shared__ float Ts[32][WW];
    const int q  = blockIdx.x;
    const int k0 = blockIdx.y * 32;
    const int t  = threadIdx.x;
    for (int idx = t; idx < WW*HH; idx += 256) Ps[idx] = params[idx];
    for (int idx = t; idx < 32*WW; idx += 256) {
        int kk = idx / WW, w = idx - kk*WW;
        int kg = k0 + kk;
        Ts[kk][w] = (kg < LL) ? table[(q*LL + kg)*WW + w] : 0.f;
    }
    __syncthreads();
    for (int idx = t; idx < 32*HH; idx += 256) {
        int kk = idx / HH, h = idx - kk*HH;
        int kg = k0 + kk;
        if (kg >= LL) continue;
        float s = 0.f;
        #pragma unroll
        for (int w = 0; w < WW; w++) s += Ts[kk][w] * Ps[w*HH + h];
        if (q == kg) s += 1.f;
        g_TR[(h*LL + q)*LL + kg] = s;
    }
}

// ---------------- stage B: qkv GEMM  (X[M,768] @ W[768,2304] + b) -------------
// 128x128 block tile, 32 k-tile, 256 threads, 8x8 per-thread, float4 LDS
__global__ __launch_bounds__(256) void gemm_qkv(
    const float* __restrict__ X, const float* __restrict__ Wt,
    const float* __restrict__ bias)
{
    __shared__ float As[32][128];  // [k][m]
    __shared__ float Bs[32][128];  // [k][n]
    const int t  = threadIdx.x;
    const int tx = t & 15, ty = t >> 4;
    const int m0 = blockIdx.y * 128;
    const int n0 = blockIdx.x * 128;
    float acc[8][8];
    #pragma unroll
    for (int i = 0; i < 8; i++)
        #pragma unroll
        for (int j = 0; j < 8; j++) acc[i][j] = 0.f;

    const int arow = t >> 1;           // 0..127
    const int akb  = (t & 1) * 8;      // 0 or 8   (k segments akb, akb+16)
    const int brow = t >> 4;           // 0..15    (rows brow, brow+16)
    const int bcol = (t & 15) * 8;     // 0..120

    for (int k0 = 0; k0 < CC; k0 += 32) {
        int gr = m0 + arow;
        float4 a0, a1;
        if (gr < MM) {
            const float* p = X + (long)gr*CC + k0 + akb;
            a0 = *(const float4*)p; a1 = *(const float4*)(p + 4);
        } else { a0 = make_float4(0,0,0,0); a1 = a0; }
        As[akb+0][arow]=a0.x; As[akb+1][arow]=a0.y; As[akb+2][arow]=a0.z; As[akb+3][arow]=a0.w;
        As[akb+4][arow]=a1.x; As[akb+5][arow]=a1.y; As[akb+6][arow]=a1.z; As[akb+7][arow]=a1.w;
        if (gr < MM) {
            const float* p = X + (long)gr*CC + k0 + 16 + akb;
            a0 = *(const float4*)p; a1 = *(const float4*)(p + 4);
        } else { a0 = make_float4(0,0,0,0); a1 = a0; }
        As[16+akb+0][arow]=a0.x; As[16+akb+1][arow]=a0.y; As[16+akb+2][arow]=a0.z; As[16+akb+3][arow]=a0.w;
        As[16+akb+4][arow]=a1.x; As[16+akb+5][arow]=a1.y; As[16+akb+6][arow]=a1.z; As[16+akb+7][arow]=a1.w;
        const float* qp = Wt + (long)(k0 + brow)*NC3 + n0 + bcol;
        float4 b0 = *(const float4*)qp;
        float4 b1 = *(const float4*)(qp + 4);
        *(float4*)&Bs[brow][bcol]   = b0;
        *(float4*)&Bs[brow][bcol+4] = b1;
        const float* qp2 = Wt + (long)(k0 + 16 + brow)*NC3 + n0 + bcol;
        b0 = *(const float4*)qp2;
        b1 = *(const float4*)(qp2 + 4);
        *(float4*)&Bs[brow+16][bcol]   = b0;
        *(float4*)&Bs[brow+16][bcol+4] = b1;
        __syncthreads();
        #pragma unroll
        for (int kk = 0; kk < 32; kk++) {
            const float4 av0 = *(const float4*)&As[kk][ty*8];
            const float4 av1 = *(const float4*)&As[kk][ty*8 + 4];
            const float4 bv0 = *(const float4*)&Bs[kk][tx*8];
            const float4 bv1 = *(const float4*)&Bs[kk][tx*8 + 4];
            float a[8], bb[8];
            a[0]=av0.x; a[1]=av0.y; a[2]=av0.z; a[3]=av0.w;
            a[4]=av1.x; a[5]=av1.y; a[6]=av1.z; a[7]=av1.w;
            bb[0]=bv0.x; bb[1]=bv0.y; bb[2]=bv0.z; bb[3]=bv0.w;
            bb[4]=bv1.x; bb[5]=bv1.y; bb[6]=bv1.z; bb[7]=bv1.w;
            #pragma unroll
            for (int i = 0; i < 8; i++)
                #pragma unroll
                for (int j = 0; j < 8; j++) acc[i][j] += a[i] * bb[j];
        }
        __syncthreads();
    }
    // epilogue: scatter to Q/K/V [b][h][n][d]
    #pragma unroll
    for (int i = 0; i < 8; i++) {
        int row = m0 + ty*8 + i;
        if (row >= MM) continue;
        int b_ = row / NN, n_ = row - b_*NN;
        #pragma unroll
        for (int j = 0; j < 8; j++) {
            int col = n0 + tx*8 + j;
            float v = acc[i][j] + bias[col];
            int which = col / CC;
            int rem   = col - which*CC;
            int h = rem >> 6, d = rem & 63;
            float* dst = (which == 0) ? g_Q : (which == 1) ? g_K : g_V;
            dst[(((long)(b_*HH) + h)*NN + n_)*DD + d] = v;
        }
    }
}

// ---------------- cls row: Q2[b,h,0,:] = Q[b,h,0,:] * scale ------------------
__global__ void cls_scale()
{
    int idx = blockIdx.x * blockDim.x + threadIdx.x;
    if (idx >= BB*HH*DD) return;
    int bh = idx >> 6, d = idx & 63;
    g_Q2[(long)bh*NN*DD + d] = g_Q[(long)bh*NN*DD + d] * QSCALE;
}

// ---------------- stage C: q_patch = trans[h] @ Q[b,h,1:,:] * scale ----------
// per (b,h): [196x196] @ [196x64]; block: 64x64 out tile, 256 thr, 4x4/thread
__global__ __launch_bounds__(256) void qtrans_kernel()
{
    __shared__ float As[16][64];  // [k][q]
    __shared__ float Bs[16][64];  // [k][d]
    const int bh = blockIdx.y;
    const int q0 = blockIdx.x * 64;
    const int h  = bh % HH;
    const int t  = threadIdx.x;
    const int tx = t & 15, ty = t >> 4;
    float acc[4][4];
    #pragma unroll
    for (int i = 0; i < 4; i++)
        #pragma unroll
        for (int j = 0; j < 4; j++) acc[i][j] = 0.f;

    const float* tbase = g_TR + (long)h*LL*LL;
    const float* qbase = g_Q + ((long)bh*NN + 1)*DD;  // rows 1..196 by k index

    const int aq  = t >> 2;            // 0..63
    const int akb = (t & 3) * 4;       // 0..12
    const int bk  = t >> 4;            // 0..15
    const int bd  = (t & 15) * 4;      // 0..60

    for (int k0 = 0; k0 < LL; k0 += 16) {
        float4 av = make_float4(0,0,0,0);
        if (q0 + aq < LL) {
            const float* p = tbase + (long)(q0 + aq)*LL + k0 + akb;
            if (k0 + akb + 3 < LL) av = *(const float4*)p;
            else {
                float tmp[4] = {0,0,0,0};
                for (int j = 0; j < 4; j++) if (k0 + akb + j < LL) tmp[j] = p[j];
                av = make_float4(tmp[0], tmp[1], tmp[2], tmp[3]);
            }
        }
        As[akb+0][aq] = av.x; As[akb+1][aq] = av.y;
        As[akb+2][aq] = av.z; As[akb+3][aq] = av.w;

        float4 bv = make_float4(0,0,0,0);
        if (k0 + bk < LL) bv = *(const float4*)(qbase + (long)(k0 + bk)*DD + bd);
        *(float4*)&Bs[bk][bd] = bv;
        __syncthreads();
        #pragma unroll
        for (int kk = 0; kk < 16; kk++) {
            const float4 a4 = *(const float4*)&As[kk][ty*4];
            const float4 b4 = *(const float4*)&Bs[kk][tx*4];
            float a[4], bb[4];
            a[0]=a4.x; a[1]=a4.y; a[2]=a4.z; a[3]=a4.w;
            bb[0]=b4.x; bb[1]=b4.y; bb[2]=b4.z; bb[3]=b4.w;
            #pragma unroll
            for (int i = 0; i < 4; i++)
                #pragma unroll
                for (int j = 0; j < 4; j++) acc[i][j] += a[i] * bb[j];
        }
        __syncthreads();
    }
    #pragma unroll
    for (int i = 0; i < 4; i++) {
        int qg = q0 + ty*4 + i;
        if (qg >= LL) continue;
        #pragma unroll
        for (int j = 0; j < 4; j++)
            g_Q2[((long)bh*NN + 1 + qg)*DD + tx*4 + j] = acc[i][j] * QSCALE;
    }
}

// ---------------- stage D: attention per (b,h), 32 q rows per block ----------
__global__ __launch_bounds__(256) void attn_kernel()
{
    __shared__ float Qs[32][64];
    __shared__ float KVs[32][68];   // stride 68 floats: 16B-aligned rows
    __shared__ float Ss[32][200];   // 800B row stride (16B multiple)
    const int bh = blockIdx.y;
    const int b  = bh / HH, h = bh - b*HH;
    const int q0 = blockIdx.x * 32;
    const int t  = threadIdx.x;
    const float* qb = g_Q2 + (long)bh*NN*DD;
    const float* kb = g_K  + (long)bh*NN*DD;
    const float* vb = g_V  + (long)bh*NN*DD;

    const int lr = t >> 3;            // 0..31
    const int lc = (t & 7) * 8;       // 0..56
    {   // load Q tile
        float4 v0 = make_float4(0,0,0,0), v1 = v0;
        if (q0 + lr < NN) {
            const float* p = qb + (long)(q0 + lr)*DD + lc;
            v0 = *(const float4*)p; v1 = *(const float4*)(p + 4);
        }
        *(float4*)&Qs[lr][lc]     = v0;
        *(float4*)&Qs[lr][lc + 4] = v1;
    }

    const int kj  = t & 31;
    const int qib = t >> 5;           // 0..7
    for (int kt = 0; kt < 7; kt++) {
        int ks = kt * 32;
        int nk = (NN - ks < 32) ? (NN - ks) : 32;
        __syncthreads();
        {   // load K tile (zeros beyond seq end)
            float v[8] = {0,0,0,0,0,0,0,0};
            if (ks + lr < NN) {
                const float4 a = *(const float4*)(kb + (long)(ks + lr)*DD + lc);
                const float4 c = *(const float4*)(kb + (long)(ks + lr)*DD + lc + 4);
                v[0]=a.x; v[1]=a.y; v[2]=a.z; v[3]=a.w;
                v[4]=c.x; v[5]=c.y; v[6]=c.z; v[7]=c.w;
            }
            #pragma unroll
            for (int j = 0; j < 8; j++) KVs[lr][lc + j] = v[j];
        }
        __syncthreads();
        // S = Q @ K^T : 4 q-rows per thread, float4 over d
        {
            float s0 = 0.f, s1 = 0.f, s2 = 0.f, s3 = 0.f;
            #pragma unroll
            for (int d0 = 0; d0 < 64; d0 += 4) {
                const float4 kv = *(const float4*)&KVs[kj][d0];
                const float4 qa = *(const float4*)&Qs[qib     ][d0];
                const float4 qc = *(const float4*)&Qs[qib +  8][d0];
                const float4 qe = *(const float4*)&Qs[qib + 16][d0];
                const float4 qg = *(const float4*)&Qs[qib + 24][d0];
                s0 += qa.x*kv.x + qa.y*kv.y + qa.z*kv.z + qa.w*kv.w;
                s1 += qc.x*kv.x + qc.y*kv.y + qc.z*kv.z + qc.w*kv.w;
                s2 += qe.x*kv.x + qe.y*kv.y + qe.z*kv.z + qe.w*kv.w;
                s3 += qg.x*kv.x + qg.y*kv.y + qg.z*kv.z + qg.w*kv.w;
            }
            if (kj < nk) {
                Ss[qib     ][ks + kj] = s0;
                Ss[qib +  8][ks + kj] = s1;
                Ss[qib + 16][ks + kj] = s2;
                Ss[qib + 24][ks + kj] = s3;
            }
        }
    }
    __syncthreads();

    // softmax: 8 lanes per row
    {
        const int r  = t >> 3;
        const int l8 = t & 7;
        float mx = -1e30f;
        for (int c = l8; c < NN; c += 8) mx = fmaxf(mx, Ss[r][c]);
        #pragma unroll
        for (int o = 1; o < 8; o <<= 1) mx = fmaxf(mx, __shfl_xor_sync(0xffffffffu, mx, o));
        float sm = 0.f;
        for (int c = l8; c < NN; c += 8) { float e = __expf(Ss[r][c] - mx); Ss[r][c] = e; sm += e; }
        #pragma unroll
        for (int o = 1; o < 8; o <<= 1) sm += __shfl_xor_sync(0xffffffffu, sm, o);
        float inv = 1.f / sm;
        for (int c = l8; c < NN; c += 8) Ss[r][c] *= inv;
    }

    // O = P @ V : float4 over kk (Ss rows contiguous in kk)
    const int d    = t & 63;
    const int qib2 = t >> 6;          // 0..3
    float o[8];
    #pragma unroll
    for (int p = 0; p < 8; p++) o[p] = 0.f;
    for (int kt = 0; kt < 7; kt++) {
        int ks = kt * 32;
        int nk = (NN - ks < 32) ? (NN - ks) : 32;
        __syncthreads();
        {   // load V tile
            float v[8] = {0,0,0,0,0,0,0,0};
            if (ks + lr < NN) {
                const float4 a = *(const float4*)(vb + (long)(ks + lr)*DD + lc);
                const float4 c = *(const float4*)(vb + (long)(ks + lr)*DD + lc + 4);
                v[0]=a.x; v[1]=a.y; v[2]=a.z; v[3]=a.w;
                v[4]=c.x; v[5]=c.y; v[6]=c.z; v[7]=c.w;
            }
            #pragma unroll
            for (int j = 0; j < 8; j++) KVs[lr][lc + j] = v[j];
        }
        __syncthreads();
        int kk = 0;
        for (; kk + 3 < nk; kk += 4) {
            const float vv0 = KVs[kk+0][d];
            const float vv1 = KVs[kk+1][d];
            const float vv2 = KVs[kk+2][d];
            const float vv3 = KVs[kk+3][d];
            #pragma unroll
            for (int p = 0; p < 8; p++) {
                const float4 sv = *(const float4*)&Ss[qib2 + p*4][ks + kk];
                o[p] += sv.x*vv0 + sv.y*vv1 + sv.z*vv2 + sv.w*vv3;
            }
        }
        for (; kk < nk; kk++) {
            const float vv = KVs[kk][d];
            #pragma unroll
            for (int p = 0; p < 8; p++) o[p] += Ss[qib2 + p*4][ks + kk] * vv;
        }
    }
    #pragma unroll
    for (int p = 0; p < 8; p++) {
        int qg = q0 + qib2 + p*4;
        if (qg < NN) g_ATT[((long)b*NN + qg)*CC + h*DD + d] = o[p];
    }
}

// ---------------- stage E: proj GEMM  (ATT[M,768] @ W[768,768] + b) ----------
__global__ __launch_bounds__(256) void gemm_proj(
    const float* __restrict__ Wt, const float* __restrict__ bias,
    float* __restrict__ Out)
{
    __shared__ float As[32][128];
    __shared__ float Bs[32][128];
    const int t  = threadIdx.x;
    const int tx = t & 15, ty = t >> 4;
    const int m0 = blockIdx.y * 128;
    const int n0 = blockIdx.x * 128;
    float acc[8][8];
    #pragma unroll
    for (int i = 0; i < 8; i++)
        #pragma unroll
        for (int j = 0; j < 8; j++) acc[i][j] = 0.f;

    const int arow = t >> 1;
    const int akb  = (t & 1) * 8;
    const int brow = t >> 4;
    const int bcol = (t & 15) * 8;

    for (int k0 = 0; k0 < CC; k0 += 32) {
        int gr = m0 + arow;
        float4 a0, a1;
        if (gr < MM) {
            const float* p = g_ATT + (long)gr*CC + k0 + akb;
            a0 = *(const float4*)p; a1 = *(const float4*)(p + 4);
        } else { a0 = make_float4(0,0,0,0); a1 = a0; }
        As[akb+0][arow]=a0.x; As[akb+1][arow]=a0.y; As[akb+2][arow]=a0.z; As[akb+3][arow]=a0.w;
        As[akb+4][arow]=a1.x; As[akb+5][arow]=a1.y; As[akb+6][arow]=a1.z; As[akb+7][arow]=a1.w;
        if (gr < MM) {
            const float* p = g_ATT + (long)gr*CC + k0 + 16 + akb;
            a0 = *(const float4*)p; a1 = *(const float4*)(p + 4);
        } else { a0 = make_float4(0,0,0,0); a1 = a0; }
        As[16+akb+0][arow]=a0.x; As[16+akb+1][arow]=a0.y; As[16+akb+2][arow]=a0.z; As[16+akb+3][arow]=a0.w;
        As[16+akb+4][arow]=a1.x; As[16+akb+5][arow]=a1.y; As[16+akb+6][arow]=a1.z; As[16+akb+7][arow]=a1.w;
        const float* qp = Wt + (long)(k0 + brow)*CC + n0 + bcol;
        float4 b0 = *(const float4*)qp;
        float4 b1 = *(const float4*)(qp + 4);
        *(float4*)&Bs[brow][bcol]   = b0;
        *(float4*)&Bs[brow][bcol+4] = b1;
        const float* qp2 = Wt + (long)(k0 + 16 + brow)*CC + n0 + bcol;
        b0 = *(const float4*)qp2;
        b1 = *(const float4*)(qp2 + 4);
        *(float4*)&Bs[brow+16][bcol]   = b0;
        *(float4*)&Bs[brow+16][bcol+4] = b1;
        __syncthreads();
        #pragma unroll
        for (int kk = 0; kk < 32; kk++) {
            const float4 av0 = *(const float4*)&As[kk][ty*8];
            const float4 av1 = *(const float4*)&As[kk][ty*8 + 4];
            const float4 bv0 = *(const float4*)&Bs[kk][tx*8];
            const float4 bv1 = *(const float4*)&Bs[kk][tx*8 + 4];
            float a[8], bb[8];
            a[0]=av0.x; a[1]=av0.y; a[2]=av0.z; a[3]=av0.w;
            a[4]=av1.x; a[5]=av1.y; a[6]=av1.z; a[7]=av1.w;
            bb[0]=bv0.x; bb[1]=bv0.y; bb[2]=bv0.z; bb[3]=bv0.w;
            bb[4]=bv1.x; bb[5]=bv1.y; bb[6]=bv1.z; bb[7]=bv1.w;
            #pragma unroll
            for (int i = 0; i < 8; i++)
                #pragma unroll
                for (int j = 0; j < 8; j++) acc[i][j] += a[i] * bb[j];
        }
        __syncthreads();
    }
    #pragma unroll
    for (int i = 0; i < 8; i++) {
        int row = m0 + ty*8 + i;
        if (row >= MM) continue;
        #pragma unroll
        for (int j = 0; j < 8; j++) {
            int col = n0 + tx*8 + j;
            Out[(long)row*CC + col] = acc[i][j] + bias[col];
        }
    }
}

// ---------------- launch ------------------------------------------------------
extern "C" void kernel_launch(void* const* d_in, const int* in_sizes, int n_in,
                              void* d_out, int out_size)
{
    (void)in_sizes; (void)n_in; (void)out_size;
    const float* x      = (const float*)d_in[0];
    const float* qkv_w  = (const float*)d_in[1];
    const float* qkv_b  = (const float*)d_in[2];
    const float* proj_w = (const float*)d_in[3];
    const float* proj_b = (const float*)d_in[4];
    const float* table  = (const float*)d_in[5];
    const float* params = (const float*)d_in[6];
    float* out = (float*)d_out;

    trans_kernel<<<dim3(LL, 7), 256>>>(table, params);
    gemm_qkv<<<dim3(NC3/128, (MM + 127)/128), 256>>>(x, qkv_w, qkv_b);
    cls_scale<<<(BB*HH*DD + 255)/256, 256>>>();
    qtrans_kernel<<<dim3((LL + 63)/64, BB*HH), 256>>>();
    attn_kernel<<<dim3((NN + 31)/32, BB*HH), 256>>>();
    gemm_proj<<<dim3(CC/128, (MM + 127)/128), 256>>>(proj_w, proj_b, out);
}

// round 16
// speedup vs baseline: 1.0756x; 1.0131x over previous

#include <cuda_runtime.h>

#define BB 64
#define NN 197
#define CC 768
#define HH 12
#define DD 64
#define LL 196
#define WW 72
#define MM (BB*NN)        // 12608
#define NC3 (3*CC)        // 2304
#define QSCALE 0.125f     // D^-0.5

// ---------------- scratch (static device globals; no allocs allowed) ----------
__device__ float g_Q  [BB*HH*NN*DD];   // [b][h][n][d]
__device__ float g_K  [BB*HH*NN*DD];
__device__ float g_V  [BB*HH*NN*DD];
__device__ float g_Q2 [BB*HH*NN*DD];   // transformed+scaled q
__device__ float g_TR [HH*LL*LL];      // trans[h][q][k]
__device__ float g_ATT[MM*CC];         // attention out, [b][n][c]

// ---------------- stage A: trans[h][q][k] = table[q,k,:]@params[:,h] + eye ----
__global__ __launch_bounds__(256) void trans_kernel(
    const float* __restrict__ table, const float* __restrict__ params)
{
    __shared__ float Ps[WW*HH];     // params [w][h]
    __shared__ float Ts[32][WW];
    const int q  = blockIdx.x;
    const int k0 = blockIdx.y * 32;
    const int t  = threadIdx.x;
    for (int idx = t; idx < WW*HH; idx += 256) Ps[idx] = params[idx];
    for (int idx = t; idx < 32*WW; idx += 256) {
        int kk = idx / WW, w = idx - kk*WW;
        int kg = k0 + kk;
        Ts[kk][w] = (kg < LL) ? table[(q*LL + kg)*WW + w] : 0.f;
    }
    __syncthreads();
    for (int idx = t; idx < 32*HH; idx += 256) {
        int kk = idx / HH, h = idx - kk*HH;
        int kg = k0 + kk;
        if (kg >= LL) continue;
        float s = 0.f;
        #pragma unroll
        for (int w = 0; w < WW; w++) s += Ts[kk][w] * Ps[w*HH + h];
        if (q == kg) s += 1.f;
        g_TR[(h*LL + q)*LL + kg] = s;
    }
}

// ---------------- stage B: qkv GEMM  (X[M,768] @ W[768,2304] + b) -------------
// 128x128 block tile, 32 k-tile, 256 threads, 8x8 per-thread, float4 LDS
__global__ __launch_bounds__(256) void gemm_qkv(
    const float* __restrict__ X, const float* __restrict__ Wt,
    const float* __restrict__ bias)
{
    __shared__ float As[32][128];  // [k][m]
    __shared__ float Bs[32][128];  // [k][n]
    const int t  = threadIdx.x;
    const int tx = t & 15, ty = t >> 4;
    const int m0 = blockIdx.y * 128;
    const int n0 = blockIdx.x * 128;
    float acc[8][8];
    #pragma unroll
    for (int i = 0; i < 8; i++)
        #pragma unroll
        for (int j = 0; j < 8; j++) acc[i][j] = 0.f;

    const int arow = t >> 1;           // 0..127
    const int akb  = (t & 1) * 8;      // 0 or 8   (k segments akb, akb+16)
    const int brow = t >> 4;           // 0..15    (rows brow, brow+16)
    const int bcol = (t & 15) * 8;     // 0..120
    const int gr   = m0 + arow;
    const bool aok = gr < MM;

    for (int k0 = 0; k0 < CC; k0 += 32) {
        #pragma unroll
        for (int s = 0; s < 2; s++) {
            float4 a0, a1;
            if (aok) {
                const float* p = X + (long)gr*CC + k0 + s*16 + akb;
                a0 = *(const float4*)p; a1 = *(const float4*)(p + 4);
            } else { a0 = make_float4(0,0,0,0); a1 = a0; }
            As[s*16+akb+0][arow]=a0.x; As[s*16+akb+1][arow]=a0.y;
            As[s*16+akb+2][arow]=a0.z; As[s*16+akb+3][arow]=a0.w;
            As[s*16+akb+4][arow]=a1.x; As[s*16+akb+5][arow]=a1.y;
            As[s*16+akb+6][arow]=a1.z; As[s*16+akb+7][arow]=a1.w;
        }
        #pragma unroll
        for (int s = 0; s < 2; s++) {
            const float* qp = Wt + (long)(k0 + s*16 + brow)*NC3 + n0 + bcol;
            float4 b0 = *(const float4*)qp;
            float4 b1 = *(const float4*)(qp + 4);
            *(float4*)&Bs[s*16+brow][bcol]   = b0;
            *(float4*)&Bs[s*16+brow][bcol+4] = b1;
        }
        __syncthreads();
        #pragma unroll
        for (int kk = 0; kk < 32; kk++) {
            const float4 av0 = *(const float4*)&As[kk][ty*8];
            const float4 av1 = *(const float4*)&As[kk][ty*8 + 4];
            const float4 bv0 = *(const float4*)&Bs[kk][tx*8];
            const float4 bv1 = *(const float4*)&Bs[kk][tx*8 + 4];
            float a[8], bb[8];
            a[0]=av0.x; a[1]=av0.y; a[2]=av0.z; a[3]=av0.w;
            a[4]=av1.x; a[5]=av1.y; a[6]=av1.z; a[7]=av1.w;
            bb[0]=bv0.x; bb[1]=bv0.y; bb[2]=bv0.z; bb[3]=bv0.w;
            bb[4]=bv1.x; bb[5]=bv1.y; bb[6]=bv1.z; bb[7]=bv1.w;
            #pragma unroll
            for (int i = 0; i < 8; i++)
                #pragma unroll
                for (int j = 0; j < 8; j++) acc[i][j] += a[i] * bb[j];
        }
        __syncthreads();
    }
    // epilogue: scatter to Q/K/V [b][h][n][d]
    #pragma unroll
    for (int i = 0; i < 8; i++) {
        int row = m0 + ty*8 + i;
        if (row >= MM) continue;
        int b_ = row / NN, n_ = row - b_*NN;
        #pragma unroll
        for (int j = 0; j < 8; j++) {
            int col = n0 + tx*8 + j;
            float v = acc[i][j] + bias[col];
            int which = col / CC;
            int rem   = col - which*CC;
            int h = rem >> 6, d = rem & 63;
            float* dst = (which == 0) ? g_Q : (which == 1) ? g_K : g_V;
            dst[(((long)(b_*HH) + h)*NN + n_)*DD + d] = v;
        }
    }
}

// ---------------- cls row: Q2[b,h,0,:] = Q[b,h,0,:] * scale ------------------
__global__ void cls_scale()
{
    int idx = blockIdx.x * blockDim.x + threadIdx.x;
    if (idx >= BB*HH*DD) return;
    int bh = idx >> 6, d = idx & 63;
    g_Q2[(long)bh*NN*DD + d] = g_Q[(long)bh*NN*DD + d] * QSCALE;
}

// ---------------- stage C: q_patch = trans[h] @ Q[b,h,1:,:] * scale ----------
// per (b,h): [196x196] @ [196x64]; block: 128x64 out tile, 256 thr, 8x4/thread
__global__ __launch_bounds__(256) void qtrans_kernel()
{
    __shared__ float As[16][128];  // [k][q]
    __shared__ float Bs[16][64];   // [k][d]
    const int bh = blockIdx.y;
    const int q0 = blockIdx.x * 128;
    const int h  = bh % HH;
    const int t  = threadIdx.x;
    const int tx = t & 15, ty = t >> 4;
    float acc[8][4];
    #pragma unroll
    for (int i = 0; i < 8; i++)
        #pragma unroll
        for (int j = 0; j < 4; j++) acc[i][j] = 0.f;

    const float* tbase = g_TR + (long)h*LL*LL;
    const float* qbase = g_Q + ((long)bh*NN + 1)*DD;  // rows 1..196 by k index

    const int aq  = t >> 1;            // 0..127 (q row within tile)
    const int akb = (t & 1) * 8;       // 0 or 8 (k offset)
    const int bk  = t >> 4;            // 0..15
    const int bd  = (t & 15) * 4;      // 0..60

    for (int k0 = 0; k0 < LL; k0 += 16) {
        float4 a0 = make_float4(0,0,0,0), a1 = a0;
        if (q0 + aq < LL) {
            const float* p = tbase + (long)(q0 + aq)*LL + k0 + akb;
            if (k0 + akb + 7 < LL) { a0 = *(const float4*)p; a1 = *(const float4*)(p + 4); }
            else {
                float u0=0.f,u1=0.f,u2=0.f,u3=0.f,u4=0.f,u5=0.f,u6=0.f,u7=0.f;
                if (k0 + akb + 0 < LL) u0 = p[0];
                if (k0 + akb + 1 < LL) u1 = p[1];
                if (k0 + akb + 2 < LL) u2 = p[2];
                if (k0 + akb + 3 < LL) u3 = p[3];
                if (k0 + akb + 4 < LL) u4 = p[4];
                if (k0 + akb + 5 < LL) u5 = p[5];
                if (k0 + akb + 6 < LL) u6 = p[6];
                if (k0 + akb + 7 < LL) u7 = p[7];
                a0 = make_float4(u0,u1,u2,u3); a1 = make_float4(u4,u5,u6,u7);
            }
        }
        As[akb+0][aq]=a0.x; As[akb+1][aq]=a0.y; As[akb+2][aq]=a0.z; As[akb+3][aq]=a0.w;
        As[akb+4][aq]=a1.x; As[akb+5][aq]=a1.y; As[akb+6][aq]=a1.z; As[akb+7][aq]=a1.w;

        float4 bv = make_float4(0,0,0,0);
        if (k0 + bk < LL) bv = *(const float4*)(qbase + (long)(k0 + bk)*DD + bd);
        *(float4*)&Bs[bk][bd] = bv;
        __syncthreads();
        #pragma unroll
        for (int kk = 0; kk < 16; kk++) {
            const float4 a40 = *(const float4*)&As[kk][ty*8];
            const float4 a41 = *(const float4*)&As[kk][ty*8 + 4];
            const float4 b4  = *(const float4*)&Bs[kk][tx*4];
            float a[8], bb[4];
            a[0]=a40.x; a[1]=a40.y; a[2]=a40.z; a[3]=a40.w;
            a[4]=a41.x; a[5]=a41.y; a[6]=a41.z; a[7]=a41.w;
            bb[0]=b4.x; bb[1]=b4.y; bb[2]=b4.z; bb[3]=b4.w;
            #pragma unroll
            for (int i = 0; i < 8; i++)
                #pragma unroll
                for (int j = 0; j < 4; j++) acc[i][j] += a[i] * bb[j];
        }
        __syncthreads();
    }
    #pragma unroll
    for (int i = 0; i < 8; i++) {
        int qg = q0 + ty*8 + i;
        if (qg >= LL) continue;
        #pragma unroll
        for (int j = 0; j < 4; j++)
            g_Q2[((long)bh*NN + 1 + qg)*DD + tx*4 + j] = acc[i][j] * QSCALE;
    }
}

// ---------------- stage D: attention per (b,h), 32 q rows per block ----------
__global__ __launch_bounds__(256) void attn_kernel()
{
    __shared__ float Qs[32][64];
    __shared__ float KVs[32][68];   // stride 68 floats: 16B-aligned rows
    __shared__ float Ss[32][200];   // 800B row stride (16B multiple)
    const int bh = blockIdx.y;
    const int b  = bh / HH, h = bh - b*HH;
    const int q0 = blockIdx.x * 32;
    const int t  = threadIdx.x;
    const float* qb = g_Q2 + (long)bh*NN*DD;
    const float* kb = g_K  + (long)bh*NN*DD;
    const float* vb = g_V  + (long)bh*NN*DD;

    const int lr = t >> 3;            // 0..31
    const int lc = (t & 7) * 8;       // 0..56
    {   // load Q tile
        float4 v0 = make_float4(0,0,0,0), v1 = v0;
        if (q0 + lr < NN) {
            const float* p = qb + (long)(q0 + lr)*DD + lc;
            v0 = *(const float4*)p; v1 = *(const float4*)(p + 4);
        }
        *(float4*)&Qs[lr][lc]     = v0;
        *(float4*)&Qs[lr][lc + 4] = v1;
    }

    const int kj  = t & 31;
    const int qib = t >> 5;           // 0..7
    for (int kt = 0; kt < 7; kt++) {
        int ks = kt * 32;
        int nk = (NN - ks < 32) ? (NN - ks) : 32;
        __syncthreads();
        {   // load K tile (zeros beyond seq end)
            float v[8] = {0,0,0,0,0,0,0,0};
            if (ks + lr < NN) {
                const float4 a = *(const float4*)(kb + (long)(ks + lr)*DD + lc);
                const float4 c = *(const float4*)(kb + (long)(ks + lr)*DD + lc + 4);
                v[0]=a.x; v[1]=a.y; v[2]=a.z; v[3]=a.w;
                v[4]=c.x; v[5]=c.y; v[6]=c.z; v[7]=c.w;
            }
            #pragma unroll
            for (int j = 0; j < 8; j++) KVs[lr][lc + j] = v[j];
        }
        __syncthreads();
        // S = Q @ K^T : 4 q-rows per thread, float4 over d
        {
            float s0 = 0.f, s1 = 0.f, s2 = 0.f, s3 = 0.f;
            #pragma unroll
            for (int d0 = 0; d0 < 64; d0 += 4) {
                const float4 kv = *(const float4*)&KVs[kj][d0];
                const float4 qa = *(const float4*)&Qs[qib     ][d0];
                const float4 qc = *(const float4*)&Qs[qib +  8][d0];
                const float4 qe = *(const float4*)&Qs[qib + 16][d0];
                const float4 qg = *(const float4*)&Qs[qib + 24][d0];
                s0 += qa.x*kv.x + qa.y*kv.y + qa.z*kv.z + qa.w*kv.w;
                s1 += qc.x*kv.x + qc.y*kv.y + qc.z*kv.z + qc.w*kv.w;
                s2 += qe.x*kv.x + qe.y*kv.y + qe.z*kv.z + qe.w*kv.w;
                s3 += qg.x*kv.x + qg.y*kv.y + qg.z*kv.z + qg.w*kv.w;
            }
            if (kj < nk) {
                Ss[qib     ][ks + kj] = s0;
                Ss[qib +  8][ks + kj] = s1;
                Ss[qib + 16][ks + kj] = s2;
                Ss[qib + 24][ks + kj] = s3;
            }
        }
    }
    __syncthreads();

    // softmax: 8 lanes per row
    {
        const int r  = t >> 3;
        const int l8 = t & 7;
        float mx = -1e30f;
        for (int c = l8; c < NN; c += 8) mx = fmaxf(mx, Ss[r][c]);
        #pragma unroll
        for (int o = 1; o < 8; o <<= 1) mx = fmaxf(mx, __shfl_xor_sync(0xffffffffu, mx, o));
        float sm = 0.f;
        for (int c = l8; c < NN; c += 8) { float e = __expf(Ss[r][c] - mx); Ss[r][c] = e; sm += e; }
        #pragma unroll
        for (int o = 1; o < 8; o <<= 1) sm += __shfl_xor_sync(0xffffffffu, sm, o);
        float inv = 1.f / sm;
        for (int c = l8; c < NN; c += 8) Ss[r][c] *= inv;
    }

    // O = P @ V : float4 over kk (Ss rows contiguous in kk)
    const int d    = t & 63;
    const int qib2 = t >> 6;          // 0..3
    float o[8];
    #pragma unroll
    for (int p = 0; p < 8; p++) o[p] = 0.f;
    for (int kt = 0; kt < 7; kt++) {
        int ks = kt * 32;
        int nk = (NN - ks < 32) ? (NN - ks) : 32;
        __syncthreads();
        {   // load V tile
            float v[8] = {0,0,0,0,0,0,0,0};
            if (ks + lr < NN) {
                const float4 a = *(const float4*)(vb + (long)(ks + lr)*DD + lc);
                const float4 c = *(const float4*)(vb + (long)(ks + lr)*DD + lc + 4);
                v[0]=a.x; v[1]=a.y; v[2]=a.z; v[3]=a.w;
                v[4]=c.x; v[5]=c.y; v[6]=c.z; v[7]=c.w;
            }
            #pragma unroll
            for (int j = 0; j < 8; j++) KVs[lr][lc + j] = v[j];
        }
        __syncthreads();
        int kk = 0;
        for (; kk + 3 < nk; kk += 4) {
            const float vv0 = KVs[kk+0][d];
            const float vv1 = KVs[kk+1][d];
            const float vv2 = KVs[kk+2][d];
            const float vv3 = KVs[kk+3][d];
            #pragma unroll
            for (int p = 0; p < 8; p++) {
                const float4 sv = *(const float4*)&Ss[qib2 + p*4][ks + kk];
                o[p] += sv.x*vv0 + sv.y*vv1 + sv.z*vv2 + sv.w*vv3;
            }
        }
        for (; kk < nk; kk++) {
            const float vv = KVs[kk][d];
            #pragma unroll
            for (int p = 0; p < 8; p++) o[p] += Ss[qib2 + p*4][ks + kk] * vv;
        }
    }
    #pragma unroll
    for (int p = 0; p < 8; p++) {
        int qg = q0 + qib2 + p*4;
        if (qg < NN) g_ATT[((long)b*NN + qg)*CC + h*DD + d] = o[p];
    }
}

// ---------------- stage E: proj GEMM  (ATT[M,768] @ W[768,768] + b) ----------
__global__ __launch_bounds__(256) void gemm_proj(
    const float* __restrict__ Wt, const float* __restrict__ bias,
    float* __restrict__ Out)
{
    __shared__ float As[32][128];
    __shared__ float Bs[32][128];
    const int t  = threadIdx.x;
    const int tx = t & 15, ty = t >> 4;
    const int m0 = blockIdx.y * 128;
    const int n0 = blockIdx.x * 128;
    float acc[8][8];
    #pragma unroll
    for (int i = 0; i < 8; i++)
        #pragma unroll
        for (int j = 0; j < 8; j++) acc[i][j] = 0.f;

    const int arow = t >> 1;
    const int akb  = (t & 1) * 8;
    const int brow = t >> 4;
    const int bcol = (t & 15) * 8;
    const int gr   = m0 + arow;
    const bool aok = gr < MM;

    for (int k0 = 0; k0 < CC; k0 += 32) {
        #pragma unroll
        for (int s = 0; s < 2; s++) {
            float4 a0, a1;
            if (aok) {
                const float* p = g_ATT + (long)gr*CC + k0 + s*16 + akb;
                a0 = *(const float4*)p; a1 = *(const float4*)(p + 4);
            } else { a0 = make_float4(0,0,0,0); a1 = a0; }
            As[s*16+akb+0][arow]=a0.x; As[s*16+akb+1][arow]=a0.y;
            As[s*16+akb+2][arow]=a0.z; As[s*16+akb+3][arow]=a0.w;
            As[s*16+akb+4][arow]=a1.x; As[s*16+akb+5][arow]=a1.y;
            As[s*16+akb+6][arow]=a1.z; As[s*16+akb+7][arow]=a1.w;
        }
        #pragma unroll
        for (int s = 0; s < 2; s++) {
            const float* qp = Wt + (long)(k0 + s*16 + brow)*CC + n0 + bcol;
            float4 b0 = *(const float4*)qp;
            float4 b1 = *(const float4*)(qp + 4);
            *(float4*)&Bs[s*16+brow][bcol]   = b0;
            *(float4*)&Bs[s*16+brow][bcol+4] = b1;
        }
        __syncthreads();
        #pragma unroll
        for (int kk = 0; kk < 32; kk++) {
            const float4 av0 = *(const float4*)&As[kk][ty*8];
            const float4 av1 = *(const float4*)&As[kk][ty*8 + 4];
            const float4 bv0 = *(const float4*)&Bs[kk][tx*8];
            const float4 bv1 = *(const float4*)&Bs[kk][tx*8 + 4];
            float a[8], bb[8];
            a[0]=av0.x; a[1]=av0.y; a[2]=av0.z; a[3]=av0.w;
            a[4]=av1.x; a[5]=av1.y; a[6]=av1.z; a[7]=av1.w;
            bb[0]=bv0.x; bb[1]=bv0.y; bb[2]=bv0.z; bb[3]=bv0.w;
            bb[4]=bv1.x; bb[5]=bv1.y; bb[6]=bv1.z; bb[7]=bv1.w;
            #pragma unroll
            for (int i = 0; i < 8; i++)
                #pragma unroll
                for (int j = 0; j < 8; j++) acc[i][j] += a[i] * bb[j];
        }
        __syncthreads();
    }
    #pragma unroll
    for (int i = 0; i < 8; i++) {
        int row = m0 + ty*8 + i;
        if (row >= MM) continue;
        #pragma unroll
        for (int j = 0; j < 8; j++) {
            int col = n0 + tx*8 + j;
            Out[(long)row*CC + col] = acc[i][j] + bias[col];
        }
    }
}

// ---------------- launch ------------------------------------------------------
extern "C" void kernel_launch(void* const* d_in, const int* in_sizes, int n_in,
                              void* d_out, int out_size)
{
    (void)in_sizes; (void)n_in; (void)out_size;
    const float* x      = (const float*)d_in[0];
    const float* qkv_w  = (const float*)d_in[1];
    const float* qkv_b  = (const float*)d_in[2];
    const float* proj_w = (const float*)d_in[3];
    const float* proj_b = (const float*)d_in[4];
    const float* table  = (const float*)d_in[5];
    const float* params = (const float*)d_in[6];
    float* out = (float*)d_out;

    trans_kernel<<<dim3(LL, 7), 256>>>(table, params);
    gemm_qkv<<<dim3(NC3/128, (MM + 127)/128), 256>>>(x, qkv_w, qkv_b);
    cls_scale<<<(BB*HH*DD + 255)/256, 256>>>();
    qtrans_kernel<<<dim3((LL + 127)/128, BB*HH), 256>>>();
    attn_kernel<<<dim3((NN + 31)/32, BB*HH), 256>>>();
    gemm_proj<<<dim3(CC/128, (MM + 127)/128), 256>>>(proj_w, proj_b, out);
}

// round 17
// speedup vs baseline: 1.0879x; 1.0114x over previous

#include <cuda_runtime.h>

#define BB 64
#define NN 197
#define CC 768
#define HH 12
#define DD 64
#define LL 196
#define WW 72
#define MM (BB*NN)        // 12608
#define NC3 (3*CC)        // 2304
#define QSCALE 0.125f     // D^-0.5

// ---------------- scratch (static device globals; no allocs allowed) ----------
__device__ float g_Q  [BB*HH*NN*DD];   // [b][h][n][d]
__device__ float g_K  [BB*HH*NN*DD];
__device__ float g_V  [BB*HH*NN*DD];
__device__ float g_Q2 [BB*HH*NN*DD];   // transformed+scaled q
__device__ float g_TR [HH*LL*LL];      // trans[h][q][k]
__device__ float g_ATT[MM*CC];         // attention out, [b][n][c]

// ---------------- packed fp32x2 helpers (Blackwell double-rate fp32) ----------
__device__ __forceinline__ unsigned long long pk2(float x, float y) {
    unsigned long long r;
    asm("mov.b64 %0, {%1, %2};" : "=l"(r) : "f"(x), "f"(y));
    return r;
}
__device__ __forceinline__ void fma2(unsigned long long& c,
                                     unsigned long long a, unsigned long long b) {
    asm("fma.rn.f32x2 %0, %1, %2, %0;" : "+l"(c) : "l"(a), "l"(b));
}
__device__ __forceinline__ float2 up2(unsigned long long v) {
    float2 r;
    asm("mov.b64 {%0, %1}, %2;" : "=f"(r.x), "=f"(r.y) : "l"(v));
    return r;
}

// ---------------- stage A: trans[h][q][k] = table[q,k,:]@params[:,h] + eye ----
__global__ __launch_bounds__(256) void trans_kernel(
    const float* __restrict__ table, const float* __restrict__ params)
{
    __shared__ float Ps[WW*HH];     // params [w][h]
    __shared__ float Ts[32][WW];
    const int q  = blockIdx.x;
    const int k0 = blockIdx.y * 32;
    const int t  = threadIdx.x;
    for (int idx = t; idx < WW*HH; idx += 256) Ps[idx] = params[idx];
    for (int idx = t; idx < 32*WW; idx += 256) {
        int kk = idx / WW, w = idx - kk*WW;
        int kg = k0 + kk;
        Ts[kk][w] = (kg < LL) ? table[(q*LL + kg)*WW + w] : 0.f;
    }
    __syncthreads();
    for (int idx = t; idx < 32*HH; idx += 256) {
        int kk = idx / HH, h = idx - kk*HH;
        int kg = k0 + kk;
        if (kg >= LL) continue;
        float s = 0.f;
        #pragma unroll
        for (int w = 0; w < WW; w++) s += Ts[kk][w] * Ps[w*HH + h];
        if (q == kg) s += 1.f;
        g_TR[(h*LL + q)*LL + kg] = s;
    }
}

// ---------------- stage B: qkv GEMM  (X[M,768] @ W[768,2304] + b) -------------
// 128x128 block tile, 32 k-tile, 256 threads, 8x8 per-thread, f32x2 FFMA
__global__ __launch_bounds__(256) void gemm_qkv(
    const float* __restrict__ X, const float* __restrict__ Wt,
    const float* __restrict__ bias)
{
    __shared__ float As[32][128];  // [k][m]
    __shared__ float Bs[32][128];  // [k][n]
    const int t  = threadIdx.x;
    const int tx = t & 15, ty = t >> 4;
    const int m0 = blockIdx.y * 128;
    const int n0 = blockIdx.x * 128;
    unsigned long long acc[8][4];  // 8 rows x 4 col-pairs (2 floats each)
    #pragma unroll
    for (int i = 0; i < 8; i++)
        #pragma unroll
        for (int j = 0; j < 4; j++) acc[i][j] = 0ull;

    const int arow = t >> 1;           // 0..127
    const int akb  = (t & 1) * 8;      // 0 or 8
    const int brow = t >> 4;           // 0..15
    const int bcol = (t & 15) * 8;     // 0..120
    const int gr   = m0 + arow;
    const bool aok = gr < MM;

    for (int k0 = 0; k0 < CC; k0 += 32) {
        #pragma unroll
        for (int s = 0; s < 2; s++) {
            float4 a0, a1;
            if (aok) {
                const float* p = X + (long)gr*CC + k0 + s*16 + akb;
                a0 = *(const float4*)p; a1 = *(const float4*)(p + 4);
            } else { a0 = make_float4(0,0,0,0); a1 = a0; }
            As[s*16+akb+0][arow]=a0.x; As[s*16+akb+1][arow]=a0.y;
            As[s*16+akb+2][arow]=a0.z; As[s*16+akb+3][arow]=a0.w;
            As[s*16+akb+4][arow]=a1.x; As[s*16+akb+5][arow]=a1.y;
            As[s*16+akb+6][arow]=a1.z; As[s*16+akb+7][arow]=a1.w;
        }
        #pragma unroll
        for (int s = 0; s < 2; s++) {
            const float* qp = Wt + (long)(k0 + s*16 + brow)*NC3 + n0 + bcol;
            float4 b0 = *(const float4*)qp;
            float4 b1 = *(const float4*)(qp + 4);
            *(float4*)&Bs[s*16+brow][bcol]   = b0;
            *(float4*)&Bs[s*16+brow][bcol+4] = b1;
        }
        __syncthreads();
        #pragma unroll
        for (int kk = 0; kk < 32; kk++) {
            const float4 av0 = *(const float4*)&As[kk][ty*8];
            const float4 av1 = *(const float4*)&As[kk][ty*8 + 4];
            const float4 bv0 = *(const float4*)&Bs[kk][tx*8];
            const float4 bv1 = *(const float4*)&Bs[kk][tx*8 + 4];
            const unsigned long long b0 = pk2(bv0.x, bv0.y);
            const unsigned long long b1 = pk2(bv0.z, bv0.w);
            const unsigned long long b2 = pk2(bv1.x, bv1.y);
            const unsigned long long b3 = pk2(bv1.z, bv1.w);
            float a[8];
            a[0]=av0.x; a[1]=av0.y; a[2]=av0.z; a[3]=av0.w;
            a[4]=av1.x; a[5]=av1.y; a[6]=av1.z; a[7]=av1.w;
            #pragma unroll
            for (int i = 0; i < 8; i++) {
                const unsigned long long ap = pk2(a[i], a[i]);
                fma2(acc[i][0], ap, b0);
                fma2(acc[i][1], ap, b1);
                fma2(acc[i][2], ap, b2);
                fma2(acc[i][3], ap, b3);
            }
        }
        __syncthreads();
    }
    // epilogue: scatter to Q/K/V [b][h][n][d]
    #pragma unroll
    for (int i = 0; i < 8; i++) {
        int row = m0 + ty*8 + i;
        if (row >= MM) continue;
        int b_ = row / NN, n_ = row - b_*NN;
        #pragma unroll
        for (int j = 0; j < 4; j++) {
            const float2 v2 = up2(acc[i][j]);
            #pragma unroll
            for (int cb = 0; cb < 2; cb++) {
                int col = n0 + tx*8 + j*2 + cb;
                float v = (cb ? v2.y : v2.x) + bias[col];
                int which = col / CC;
                int rem   = col - which*CC;
                int h = rem >> 6, d = rem & 63;
                float* dst = (which == 0) ? g_Q : (which == 1) ? g_K : g_V;
                dst[(((long)(b_*HH) + h)*NN + n_)*DD + d] = v;
            }
        }
    }
}

// ---------------- cls row: Q2[b,h,0,:] = Q[b,h,0,:] * scale ------------------
__global__ void cls_scale()
{
    int idx = blockIdx.x * blockDim.x + threadIdx.x;
    if (idx >= BB*HH*DD) return;
    int bh = idx >> 6, d = idx & 63;
    g_Q2[(long)bh*NN*DD + d] = g_Q[(long)bh*NN*DD + d] * QSCALE;
}

// ---------------- stage C: q_patch = trans[h] @ Q[b,h,1:,:] * scale ----------
// per (b,h): [196x196] @ [196x64]; block: 128x64 out tile, 256 thr, 8x4/thread
__global__ __launch_bounds__(256) void qtrans_kernel()
{
    __shared__ float As[16][128];  // [k][q]
    __shared__ float Bs[16][64];   // [k][d]
    const int bh = blockIdx.y;
    const int q0 = blockIdx.x * 128;
    const int h  = bh % HH;
    const int t  = threadIdx.x;
    const int tx = t & 15, ty = t >> 4;
    float acc[8][4];
    #pragma unroll
    for (int i = 0; i < 8; i++)
        #pragma unroll
        for (int j = 0; j < 4; j++) acc[i][j] = 0.f;

    const float* tbase = g_TR + (long)h*LL*LL;
    const float* qbase = g_Q + ((long)bh*NN + 1)*DD;  // rows 1..196 by k index

    const int aq  = t >> 1;            // 0..127 (q row within tile)
    const int akb = (t & 1) * 8;       // 0 or 8 (k offset)
    const int bk  = t >> 4;            // 0..15
    const int bd  = (t & 15) * 4;      // 0..60

    for (int k0 = 0; k0 < LL; k0 += 16) {
        float4 a0 = make_float4(0,0,0,0), a1 = a0;
        if (q0 + aq < LL) {
            const float* p = tbase + (long)(q0 + aq)*LL + k0 + akb;
            if (k0 + akb + 7 < LL) { a0 = *(const float4*)p; a1 = *(const float4*)(p + 4); }
            else {
                float u0=0.f,u1=0.f,u2=0.f,u3=0.f,u4=0.f,u5=0.f,u6=0.f,u7=0.f;
                if (k0 + akb + 0 < LL) u0 = p[0];
                if (k0 + akb + 1 < LL) u1 = p[1];
                if (k0 + akb + 2 < LL) u2 = p[2];
                if (k0 + akb + 3 < LL) u3 = p[3];
                if (k0 + akb + 4 < LL) u4 = p[4];
                if (k0 + akb + 5 < LL) u5 = p[5];
                if (k0 + akb + 6 < LL) u6 = p[6];
                if (k0 + akb + 7 < LL) u7 = p[7];
                a0 = make_float4(u0,u1,u2,u3); a1 = make_float4(u4,u5,u6,u7);
            }
        }
        As[akb+0][aq]=a0.x; As[akb+1][aq]=a0.y; As[akb+2][aq]=a0.z; As[akb+3][aq]=a0.w;
        As[akb+4][aq]=a1.x; As[akb+5][aq]=a1.y; As[akb+6][aq]=a1.z; As[akb+7][aq]=a1.w;

        float4 bv = make_float4(0,0,0,0);
        if (k0 + bk < LL) bv = *(const float4*)(qbase + (long)(k0 + bk)*DD + bd);
        *(float4*)&Bs[bk][bd] = bv;
        __syncthreads();
        #pragma unroll
        for (int kk = 0; kk < 16; kk++) {
            const float4 a40 = *(const float4*)&As[kk][ty*8];
            const float4 a41 = *(const float4*)&As[kk][ty*8 + 4];
            const float4 b4  = *(const float4*)&Bs[kk][tx*4];
            float a[8], bb[4];
            a[0]=a40.x; a[1]=a40.y; a[2]=a40.z; a[3]=a40.w;
            a[4]=a41.x; a[5]=a41.y; a[6]=a41.z; a[7]=a41.w;
            bb[0]=b4.x; bb[1]=b4.y; bb[2]=b4.z; bb[3]=b4.w;
            #pragma unroll
            for (int i = 0; i < 8; i++)
                #pragma unroll
                for (int j = 0; j < 4; j++) acc[i][j] += a[i] * bb[j];
        }
        __syncthreads();
    }
    #pragma unroll
    for (int i = 0; i < 8; i++) {
        int qg = q0 + ty*8 + i;
        if (qg >= LL) continue;
        #pragma unroll
        for (int j = 0; j < 4; j++)
            g_Q2[((long)bh*NN + 1 + qg)*DD + tx*4 + j] = acc[i][j] * QSCALE;
    }
}

// ---------------- stage D: attention per (b,h), 32 q rows per block ----------
__global__ __launch_bounds__(256) void attn_kernel()
{
    __shared__ float Qs[32][64];
    __shared__ float KVs[32][68];   // stride 68 floats: 16B-aligned rows
    __shared__ float Ss[32][200];   // 800B row stride (16B multiple)
    const int bh = blockIdx.y;
    const int b  = bh / HH, h = bh - b*HH;
    const int q0 = blockIdx.x * 32;
    const int t  = threadIdx.x;
    const float* qb = g_Q2 + (long)bh*NN*DD;
    const float* kb = g_K  + (long)bh*NN*DD;
    const float* vb = g_V  + (long)bh*NN*DD;

    const int lr = t >> 3;            // 0..31
    const int lc = (t & 7) * 8;       // 0..56
    {   // load Q tile
        float4 v0 = make_float4(0,0,0,0), v1 = v0;
        if (q0 + lr < NN) {
            const float* p = qb + (long)(q0 + lr)*DD + lc;
            v0 = *(const float4*)p; v1 = *(const float4*)(p + 4);
        }
        *(float4*)&Qs[lr][lc]     = v0;
        *(float4*)&Qs[lr][lc + 4] = v1;
    }

    const int kj  = t & 31;
    const int qib = t >> 5;           // 0..7
    for (int kt = 0; kt < 7; kt++) {
        int ks = kt * 32;
        int nk = (NN - ks < 32) ? (NN - ks) : 32;
        __syncthreads();
        {   // load K tile (zeros beyond seq end)
            float v[8] = {0,0,0,0,0,0,0,0};
            if (ks + lr < NN) {
                const float4 a = *(const float4*)(kb + (long)(ks + lr)*DD + lc);
                const float4 c = *(const float4*)(kb + (long)(ks + lr)*DD + lc + 4);
                v[0]=a.x; v[1]=a.y; v[2]=a.z; v[3]=a.w;
                v[4]=c.x; v[5]=c.y; v[6]=c.z; v[7]=c.w;
            }
            #pragma unroll
            for (int j = 0; j < 8; j++) KVs[lr][lc + j] = v[j];
        }
        __syncthreads();
        // S = Q @ K^T : 4 q-rows per thread, float4 over d
        {
            float s0 = 0.f, s1 = 0.f, s2 = 0.f, s3 = 0.f;
            #pragma unroll
            for (int d0 = 0; d0 < 64; d0 += 4) {
                const float4 kv = *(const float4*)&KVs[kj][d0];
                const float4 qa = *(const float4*)&Qs[qib     ][d0];
                const float4 qc = *(const float4*)&Qs[qib +  8][d0];
                const float4 qe = *(const float4*)&Qs[qib + 16][d0];
                const float4 qg = *(const float4*)&Qs[qib + 24][d0];
                s0 += qa.x*kv.x + qa.y*kv.y + qa.z*kv.z + qa.w*kv.w;
                s1 += qc.x*kv.x + qc.y*kv.y + qc.z*kv.z + qc.w*kv.w;
                s2 += qe.x*kv.x + qe.y*kv.y + qe.z*kv.z + qe.w*kv.w;
                s3 += qg.x*kv.x + qg.y*kv.y + qg.z*kv.z + qg.w*kv.w;
            }
            if (kj < nk) {
                Ss[qib     ][ks + kj] = s0;
                Ss[qib +  8][ks + kj] = s1;
                Ss[qib + 16][ks + kj] = s2;
                Ss[qib + 24][ks + kj] = s3;
            }
        }
    }
    __syncthreads();

    // softmax: 8 lanes per row
    {
        const int r  = t >> 3;
        const int l8 = t & 7;
        float mx = -1e30f;
        for (int c = l8; c < NN; c += 8) mx = fmaxf(mx, Ss[r][c]);
        #pragma unroll
        for (int o = 1; o < 8; o <<= 1) mx = fmaxf(mx, __shfl_xor_sync(0xffffffffu, mx, o));
        float sm = 0.f;
        for (int c = l8; c < NN; c += 8) { float e = __expf(Ss[r][c] - mx); Ss[r][c] = e; sm += e; }
        #pragma unroll
        for (int o = 1; o < 8; o <<= 1) sm += __shfl_xor_sync(0xffffffffu, sm, o);
        float inv = 1.f / sm;
        for (int c = l8; c < NN; c += 8) Ss[r][c] *= inv;
    }

    // O = P @ V : float4 over kk (Ss rows contiguous in kk)
    const int d    = t & 63;
    const int qib2 = t >> 6;          // 0..3
    float o[8];
    #pragma unroll
    for (int p = 0; p < 8; p++) o[p] = 0.f;
    for (int kt = 0; kt < 7; kt++) {
        int ks = kt * 32;
        int nk = (NN - ks < 32) ? (NN - ks) : 32;
        __syncthreads();
        {   // load V tile
            float v[8] = {0,0,0,0,0,0,0,0};
            if (ks + lr < NN) {
                const float4 a = *(const float4*)(vb + (long)(ks + lr)*DD + lc);
                const float4 c = *(const float4*)(vb + (long)(ks + lr)*DD + lc + 4);
                v[0]=a.x; v[1]=a.y; v[2]=a.z; v[3]=a.w;
                v[4]=c.x; v[5]=c.y; v[6]=c.z; v[7]=c.w;
            }
            #pragma unroll
            for (int j = 0; j < 8; j++) KVs[lr][lc + j] = v[j];
        }
        __syncthreads();
        int kk = 0;
        for (; kk + 3 < nk; kk += 4) {
            const float vv0 = KVs[kk+0][d];
            const float vv1 = KVs[kk+1][d];
            const float vv2 = KVs[kk+2][d];
            const float vv3 = KVs[kk+3][d];
            #pragma unroll
            for (int p = 0; p < 8; p++) {
                const float4 sv = *(const float4*)&Ss[qib2 + p*4][ks + kk];
                o[p] += sv.x*vv0 + sv.y*vv1 + sv.z*vv2 + sv.w*vv3;
            }
        }
        for (; kk < nk; kk++) {
            const float vv = KVs[kk][d];
            #pragma unroll
            for (int p = 0; p < 8; p++) o[p] += Ss[qib2 + p*4][ks + kk] * vv;
        }
    }
    #pragma unroll
    for (int p = 0; p < 8; p++) {
        int qg = q0 + qib2 + p*4;
        if (qg < NN) g_ATT[((long)b*NN + qg)*CC + h*DD + d] = o[p];
    }
}

// ---------------- stage E: proj GEMM  (ATT[M,768] @ W[768,768] + b) ----------
__global__ __launch_bounds__(256) void gemm_proj(
    const float* __restrict__ Wt, const float* __restrict__ bias,
    float* __restrict__ Out)
{
    __shared__ float As[32][128];
    __shared__ float Bs[32][128];
    const int t  = threadIdx.x;
    const int tx = t & 15, ty = t >> 4;
    const int m0 = blockIdx.y * 128;
    const int n0 = blockIdx.x * 128;
    unsigned long long acc[8][4];
    #pragma unroll
    for (int i = 0; i < 8; i++)
        #pragma unroll
        for (int j = 0; j < 4; j++) acc[i][j] = 0ull;

    const int arow = t >> 1;
    const int akb  = (t & 1) * 8;
    const int brow = t >> 4;
    const int bcol = (t & 15) * 8;
    const int gr   = m0 + arow;
    const bool aok = gr < MM;

    for (int k0 = 0; k0 < CC; k0 += 32) {
        #pragma unroll
        for (int s = 0; s < 2; s++) {
            float4 a0, a1;
            if (aok) {
                const float* p = g_ATT + (long)gr*CC + k0 + s*16 + akb;
                a0 = *(const float4*)p; a1 = *(const float4*)(p + 4);
            } else { a0 = make_float4(0,0,0,0); a1 = a0; }
            As[s*16+akb+0][arow]=a0.x; As[s*16+akb+1][arow]=a0.y;
            As[s*16+akb+2][arow]=a0.z; As[s*16+akb+3][arow]=a0.w;
            As[s*16+akb+4][arow]=a1.x; As[s*16+akb+5][arow]=a1.y;
            As[s*16+akb+6][arow]=a1.z; As[s*16+akb+7][arow]=a1.w;
        }
        #pragma unroll
        for (int s = 0; s < 2; s++) {
            const float* qp = Wt + (long)(k0 + s*16 + brow)*CC + n0 + bcol;
            float4 b0 = *(const float4*)qp;
            float4 b1 = *(const float4*)(qp + 4);
            *(float4*)&Bs[s*16+brow][bcol]   = b0;
            *(float4*)&Bs[s*16+brow][bcol+4] = b1;
        }
        __syncthreads();
        #pragma unroll
        for (int kk = 0; kk < 32; kk++) {
            const float4 av0 = *(const float4*)&As[kk][ty*8];
            const float4 av1 = *(const float4*)&As[kk][ty*8 + 4];
            const float4 bv0 = *(const float4*)&Bs[kk][tx*8];
            const float4 bv1 = *(const float4*)&Bs[kk][tx*8 + 4];
            const unsigned long long b0 = pk2(bv0.x, bv0.y);
            const unsigned long long b1 = pk2(bv0.z, bv0.w);
            const unsigned long long b2 = pk2(bv1.x, bv1.y);
            const unsigned long long b3 = pk2(bv1.z, bv1.w);
            float a[8];
            a[0]=av0.x; a[1]=av0.y; a[2]=av0.z; a[3]=av0.w;
            a[4]=av1.x; a[5]=av1.y; a[6]=av1.z; a[7]=av1.w;
            #pragma unroll
            for (int i = 0; i < 8; i++) {
                const unsigned long long ap = pk2(a[i], a[i]);
                fma2(acc[i][0], ap, b0);
                fma2(acc[i][1], ap, b1);
                fma2(acc[i][2], ap, b2);
                fma2(acc[i][3], ap, b3);
            }
        }
        __syncthreads();
    }
    #pragma unroll
    for (int i = 0; i < 8; i++) {
        int row = m0 + ty*8 + i;
        if (row >= MM) continue;
        #pragma unroll
        for (int j = 0; j < 4; j++) {
            const float2 v2 = up2(acc[i][j]);
            int col = n0 + tx*8 + j*2;
            Out[(long)row*CC + col]     = v2.x + bias[col];
            Out[(long)row*CC + col + 1] = v2.y + bias[col + 1];
        }
    }
}

// ---------------- launch ------------------------------------------------------
extern "C" void kernel_launch(void* const* d_in, const int* in_sizes, int n_in,
                              void* d_out, int out_size)
{
    (void)in_sizes; (void)n_in; (void)out_size;
    const float* x      = (const float*)d_in[0];
    const float* qkv_w  = (const float*)d_in[1];
    const float* qkv_b  = (const float*)d_in[2];
    const float* proj_w = (const float*)d_in[3];
    const float* proj_b = (const float*)d_in[4];
    const float* table  = (const float*)d_in[5];
    const float* params = (const float*)d_in[6];
    float* out = (float*)d_out;

    trans_kernel<<<dim3(LL, 7), 256>>>(table, params);
    gemm_qkv<<<dim3(NC3/128, (MM + 127)/128), 256>>>(x, qkv_w, qkv_b);
    cls_scale<<<(BB*HH*DD + 255)/256, 256>>>();
    qtrans_kernel<<<dim3((LL + 127)/128, BB*HH), 256>>>();
    attn_kernel<<<dim3((NN + 31)/32, BB*HH), 256>>>();
    gemm_proj<<<dim3(CC/128, (MM + 127)/128), 256>>>(proj_w, proj_b, out);
}